// round 1
// baseline (speedup 1.0000x reference)
#include <cuda_runtime.h>
#include <math.h>

#define T_SEQ 2048
#define B_BATCH 2
#define D_MODEL 1024
#define H_HEADS 16
#define HD 64
#define M_ROWS (B_BATCH * T_SEQ)   /* 4096 */
#define QKV_LD 3072

// ---------------------------------------------------------------------------
// Scratch (static __device__ — no allocations allowed anywhere)
// ---------------------------------------------------------------------------
__device__ float g_qkv[(size_t)M_ROWS * QKV_LD];     // 50.3 MB
__device__ float g_ao[(size_t)M_ROWS * D_MODEL];     // 16.8 MB
__device__ float g_cos[T_SEQ * 32];
__device__ float g_sin[T_SEQ * 32];

// ---------------------------------------------------------------------------
// RoPE tables: cos/sin(t * 10000^(-2m/64)), computed in fp64 for phase accuracy
// ---------------------------------------------------------------------------
__global__ void gen_tables_kernel() {
    int i = blockIdx.x * blockDim.x + threadIdx.x;
    if (i >= T_SEQ * 32) return;
    int t = i >> 5, m = i & 31;
    double invf = exp(-(double)(2 * m) * (log(10000.0) / 64.0));
    double ph = (double)t * invf;
    g_cos[i] = (float)cos(ph);
    g_sin[i] = (float)sin(ph);
}

// ---------------------------------------------------------------------------
// SGEMM: C[M,N] = A[M,K] @ B[K,N], all row-major, M%128==0, N%128==0, K%16==0
// 128x128 block tile, BK=16, 8x8 per thread, 256 threads.
// ---------------------------------------------------------------------------
__global__ __launch_bounds__(256) void sgemm128(
    const float* __restrict__ A, const float* __restrict__ B,
    float* __restrict__ C, int M, int N, int K)
{
    __shared__ float As[16][128];   // transposed A tile: As[k][m]
    __shared__ float Bs[16][128];   // Bs[k][n]

    const int tid  = threadIdx.x;
    const int aRow = tid >> 2;          // 0..63
    const int aCol = (tid & 3) << 2;    // 0,4,8,12
    const int bRow = tid >> 5;          // 0..7
    const int bCol = (tid & 31) << 2;   // 0..124
    const int ty = tid >> 4, tx = tid & 15;

    const float* Ab = A + (size_t)blockIdx.y * 128 * K;
    const float* Bb = B + blockIdx.x * 128;

    float acc[8][8] = {};

    for (int k0 = 0; k0 < K; k0 += 16) {
        float4 a0 = *(const float4*)(Ab + (size_t)aRow * K + k0 + aCol);
        float4 a1 = *(const float4*)(Ab + (size_t)(aRow + 64) * K + k0 + aCol);
        float4 b0 = *(const float4*)(Bb + (size_t)(k0 + bRow) * N + bCol);
        float4 b1 = *(const float4*)(Bb + (size_t)(k0 + bRow + 8) * N + bCol);

        As[aCol + 0][aRow] = a0.x; As[aCol + 1][aRow] = a0.y;
        As[aCol + 2][aRow] = a0.z; As[aCol + 3][aRow] = a0.w;
        As[aCol + 0][aRow + 64] = a1.x; As[aCol + 1][aRow + 64] = a1.y;
        As[aCol + 2][aRow + 64] = a1.z; As[aCol + 3][aRow + 64] = a1.w;
        *(float4*)&Bs[bRow][bCol]     = b0;
        *(float4*)&Bs[bRow + 8][bCol] = b1;
        __syncthreads();

        #pragma unroll
        for (int kk = 0; kk < 16; kk++) {
            float rm[8], rn[8];
            *(float4*)&rm[0] = *(const float4*)&As[kk][ty * 8];
            *(float4*)&rm[4] = *(const float4*)&As[kk][ty * 8 + 4];
            *(float4*)&rn[0] = *(const float4*)&Bs[kk][tx * 8];
            *(float4*)&rn[4] = *(const float4*)&Bs[kk][tx * 8 + 4];
            #pragma unroll
            for (int i = 0; i < 8; i++)
                #pragma unroll
                for (int j = 0; j < 8; j++)
                    acc[i][j] += rm[i] * rn[j];
        }
        __syncthreads();
    }

    float* Cb = C + (size_t)blockIdx.y * 128 * N + blockIdx.x * 128;
    #pragma unroll
    for (int i = 0; i < 8; i++) {
        float* row = Cb + (size_t)(ty * 8 + i) * N + tx * 8;
        *(float4*)row       = make_float4(acc[i][0], acc[i][1], acc[i][2], acc[i][3]);
        *(float4*)(row + 4) = make_float4(acc[i][4], acc[i][5], acc[i][6], acc[i][7]);
    }
}

// ---------------------------------------------------------------------------
// RoPE in-place on q (cols [0,1024)) and k (cols [1024,2048)) of g_qkv.
// Interleaved rotate_half: out[2i]   = x[2i]  *cos[j]   - x[2i+1]*sin[j]
//                          out[2i+1] = x[2i+1]*cos[j+1] + x[2i]  *sin[j+1]
// table index = (head-dim index) mod 32.
// One thread per even/odd pair.
// ---------------------------------------------------------------------------
__global__ void rope_apply_kernel(float* __restrict__ qkv) {
    int idx = blockIdx.x * blockDim.x + threadIdx.x;
    if (idx >= M_ROWS * 1024) return;
    int row = idx >> 10;                                  // 0..4095
    int p   = idx & 1023;                                 // pair id across q|k
    int col = ((p >> 9) << 10) + ((p & 511) << 1);        // half*1024 + pair*2
    int t = row & (T_SEQ - 1);
    int j = col & 63;                                     // even head-dim idx
    int m0 = j & 31;

    float* ptr = qkv + (size_t)row * QKV_LD + col;
    float x0 = ptr[0], x1 = ptr[1];
    const float* ct = g_cos + t * 32;
    const float* st = g_sin + t * 32;
    float c0 = ct[m0], s0 = st[m0];
    float c1 = ct[m0 + 1], s1 = st[m0 + 1];
    ptr[0] = x0 * c0 - x1 * s0;
    ptr[1] = x1 * c1 + x0 * s1;
}

// ---------------------------------------------------------------------------
// Flash attention fp32. One block = one (b, h, 64-query tile).
// 256 threads as 16x16; each thread owns a 4x4 S-subtile and 4x4 O-subtile.
// smem: Qs[j][r] (Q^T, pre-scaled), Ks[j][c] (K^T, later reused as P[c][r]),
//       Vs[c][d]; all with stride 65 to dodge bank conflicts.
// ---------------------------------------------------------------------------
#define AT_STR 65

__global__ __launch_bounds__(256) void attn64_kernel(
    const float* __restrict__ qkv, float* __restrict__ ao)
{
    extern __shared__ float sm[];
    float* Qs = sm;                  // 64*65
    float* Ks = sm + 64 * AT_STR;    // 64*65 (reused for P)
    float* Vs = sm + 2 * 64 * AT_STR;

    const int tid = threadIdx.x;
    const int b = blockIdx.y >> 4, h = blockIdx.y & 15;
    const int q0 = blockIdx.x * 64;
    const float* base = qkv + (size_t)b * T_SEQ * QKV_LD + h * 64;

    // Load Q tile transposed, scale folded in (1/sqrt(64) = 0.125)
    for (int idx = tid; idx < 4096; idx += 256) {
        int r = idx >> 6, j = idx & 63;
        Qs[j * AT_STR + r] = base[(size_t)(q0 + r) * QKV_LD + j] * 0.125f;
    }

    const int ty = tid >> 4, tx = tid & 15;
    float o[4][4] = {};
    float mM[4] = {-INFINITY, -INFINITY, -INFINITY, -INFINITY};
    float lL[4] = {0.f, 0.f, 0.f, 0.f};
    __syncthreads();

    for (int s0 = 0; s0 < T_SEQ; s0 += 64) {
        // Load K tile (transposed) and V tile
        for (int idx = tid; idx < 4096; idx += 256) {
            int c = idx >> 6, j = idx & 63;
            const float* kb = base + (size_t)(s0 + c) * QKV_LD;
            Ks[j * AT_STR + c] = kb[1024 + j];
            Vs[c * AT_STR + j] = kb[2048 + j];
        }
        __syncthreads();

        // GEMM1: S = (Q*scale) K^T
        float sc[4][4] = {};
        #pragma unroll 8
        for (int j = 0; j < 64; j++) {
            float qr[4], kc[4];
            #pragma unroll
            for (int i = 0; i < 4; i++) qr[i] = Qs[j * AT_STR + ty * 4 + i];
            #pragma unroll
            for (int i = 0; i < 4; i++) kc[i] = Ks[j * AT_STR + tx * 4 + i];
            #pragma unroll
            for (int i = 0; i < 4; i++)
                #pragma unroll
                for (int c = 0; c < 4; c++)
                    sc[i][c] += qr[i] * kc[c];
        }
        __syncthreads();  // all threads done reading Ks before P overwrites it

        // Online softmax update (row reductions across the 16 tx lanes)
        #pragma unroll
        for (int i = 0; i < 4; i++) {
            float mx = fmaxf(fmaxf(sc[i][0], sc[i][1]), fmaxf(sc[i][2], sc[i][3]));
            #pragma unroll
            for (int off = 8; off >= 1; off >>= 1)
                mx = fmaxf(mx, __shfl_xor_sync(0xffffffffu, mx, off));
            float mnew = fmaxf(mM[i], mx);
            float alpha = __expf(mM[i] - mnew);
            float rs = 0.f;
            #pragma unroll
            for (int c = 0; c < 4; c++) {
                sc[i][c] = __expf(sc[i][c] - mnew);
                rs += sc[i][c];
            }
            #pragma unroll
            for (int off = 8; off >= 1; off >>= 1)
                rs += __shfl_xor_sync(0xffffffffu, rs, off);
            lL[i] = lL[i] * alpha + rs;
            mM[i] = mnew;
            #pragma unroll
            for (int d = 0; d < 4; d++) o[i][d] *= alpha;
        }

        // Write P transposed into Ks space: P[c][r]
        #pragma unroll
        for (int i = 0; i < 4; i++)
            #pragma unroll
            for (int c = 0; c < 4; c++)
                Ks[(tx * 4 + c) * AT_STR + ty * 4 + i] = sc[i][c];
        __syncthreads();

        // GEMM2: O += P V
        #pragma unroll 8
        for (int c = 0; c < 64; c++) {
            float pr[4], vv[4];
            #pragma unroll
            for (int i = 0; i < 4; i++) pr[i] = Ks[c * AT_STR + ty * 4 + i];
            #pragma unroll
            for (int i = 0; i < 4; i++) vv[i] = Vs[c * AT_STR + tx * 4 + i];
            #pragma unroll
            for (int i = 0; i < 4; i++)
                #pragma unroll
                for (int d = 0; d < 4; d++)
                    o[i][d] += pr[i] * vv[d];
        }
        __syncthreads();  // before next tile reloads Ks/Vs
    }

    // Normalize + write out in [B, T, H*hd] layout (matches transpose-back)
    #pragma unroll
    for (int i = 0; i < 4; i++) {
        float inv = 1.0f / lL[i];
        float4 v = make_float4(o[i][0] * inv, o[i][1] * inv,
                               o[i][2] * inv, o[i][3] * inv);
        *(float4*)(ao + (size_t)(b * T_SEQ + q0 + ty * 4 + i) * D_MODEL
                   + h * 64 + tx * 4) = v;
    }
}

// ---------------------------------------------------------------------------
// Launch
// ---------------------------------------------------------------------------
extern "C" void kernel_launch(void* const* d_in, const int* in_sizes, int n_in,
                              void* d_out, int out_size) {
    const float* x    = (const float*)d_in[0];
    const float* Wqkv = (const float*)d_in[1];
    const float* Wout = (const float*)d_in[2];
    float* out = (float*)d_out;

    float *qkv, *ao;
    cudaGetSymbolAddress((void**)&qkv, g_qkv);
    cudaGetSymbolAddress((void**)&ao, g_ao);

    // 1. RoPE tables
    gen_tables_kernel<<<(T_SEQ * 32 + 255) / 256, 256>>>();

    // 2. QKV projection: [4096,1024] @ [1024,3072]
    sgemm128<<<dim3(QKV_LD / 128, M_ROWS / 128), 256>>>(
        x, Wqkv, qkv, M_ROWS, QKV_LD, D_MODEL);

    // 3. RoPE in-place on q,k
    rope_apply_kernel<<<(M_ROWS * 1024) / 256, 256>>>(qkv);

    // 4. Attention
    const int smem = 3 * 64 * AT_STR * (int)sizeof(float);  // 49,920 B
    cudaFuncSetAttribute(attn64_kernel,
                         cudaFuncAttributeMaxDynamicSharedMemorySize, smem);
    attn64_kernel<<<dim3(T_SEQ / 64, B_BATCH * H_HEADS), 256, smem>>>(qkv, ao);

    // 5. Output projection: [4096,1024] @ [1024,1024]
    sgemm128<<<dim3(D_MODEL / 128, M_ROWS / 128), 256>>>(
        ao, Wout, out, M_ROWS, D_MODEL, D_MODEL);
}

// round 3
// speedup vs baseline: 1.4562x; 1.4562x over previous
#include <cuda_runtime.h>
#include <cuda_bf16.h>
#include <math.h>
#include <stdint.h>

#define T_SEQ 2048
#define B_BATCH 2
#define D_MODEL 1024
#define H_HEADS 16
#define M_ROWS 4096          /* B*T */
#define QKV_LD 3072

// ---------------------------------------------------------------------------
// Scratch (static __device__ — no allocations allowed anywhere)
// ---------------------------------------------------------------------------
__device__ float g_qkv[(size_t)M_ROWS * QKV_LD];          // 50.3 MB
__device__ float g_ao[(size_t)M_ROWS * D_MODEL];          // 16.8 MB
__device__ __nv_bfloat16 g_xhi[(size_t)M_ROWS * D_MODEL];
__device__ __nv_bfloat16 g_xlo[(size_t)M_ROWS * D_MODEL];
__device__ __nv_bfloat16 g_aohi[(size_t)M_ROWS * D_MODEL];
__device__ __nv_bfloat16 g_aolo[(size_t)M_ROWS * D_MODEL];
__device__ __nv_bfloat16 g_wqt_hi[(size_t)QKV_LD * D_MODEL];   // Wqkv^T [3072,1024]
__device__ __nv_bfloat16 g_wqt_lo[(size_t)QKV_LD * D_MODEL];
__device__ __nv_bfloat16 g_wot_hi[(size_t)D_MODEL * D_MODEL];  // Wout^T [1024,1024]
__device__ __nv_bfloat16 g_wot_lo[(size_t)D_MODEL * D_MODEL];
__device__ float g_cos[T_SEQ * 32];
__device__ float g_sin[T_SEQ * 32];

// ---------------------------------------------------------------------------
// Helpers
// ---------------------------------------------------------------------------
__device__ __forceinline__ uint32_t smem_u32(const void* p) {
    uint32_t a;
    asm("{ .reg .u64 t; cvta.to.shared.u64 t, %1; cvt.u32.u64 %0, t; }"
        : "=r"(a) : "l"(p));
    return a;
}

#define LDSM_X4(r, addr)                                                     \
    asm volatile("ldmatrix.sync.aligned.m8n8.x4.shared.b16 {%0,%1,%2,%3}, [%4];" \
        : "=r"((r)[0]), "=r"((r)[1]), "=r"((r)[2]), "=r"((r)[3])             \
        : "r"(addr))

#define MMA16816(c, a, b)                                                    \
    asm volatile("mma.sync.aligned.m16n8k16.row.col.f32.bf16.bf16.f32 "      \
        "{%0,%1,%2,%3}, {%4,%5,%6,%7}, {%8,%9}, {%0,%1,%2,%3};"              \
        : "+f"((c)[0]), "+f"((c)[1]), "+f"((c)[2]), "+f"((c)[3])             \
        : "r"((a)[0]), "r"((a)[1]), "r"((a)[2]), "r"((a)[3]),                \
          "r"((b)[0]), "r"((b)[1]))

// ---------------------------------------------------------------------------
// RoPE tables (fp64 phase for accuracy)
// ---------------------------------------------------------------------------
__global__ void gen_tables_kernel() {
    int i = blockIdx.x * blockDim.x + threadIdx.x;
    if (i >= T_SEQ * 32) return;
    int t = i >> 5, m = i & 31;
    double invf = exp(-(double)(2 * m) * (log(10000.0) / 64.0));
    double ph = (double)t * invf;
    g_cos[i] = (float)cos(ph);
    g_sin[i] = (float)sin(ph);
}

// ---------------------------------------------------------------------------
// Split fp32 -> (hi, lo) bf16
// ---------------------------------------------------------------------------
__global__ void split_kernel(const float* __restrict__ in,
                             __nv_bfloat16* __restrict__ hi,
                             __nv_bfloat16* __restrict__ lo, int n4) {
    int i = blockIdx.x * blockDim.x + threadIdx.x;
    if (i >= n4) return;
    float4 v = ((const float4*)in)[i];
    float vs[4] = {v.x, v.y, v.z, v.w};
    __nv_bfloat16 h[4], l[4];
#pragma unroll
    for (int u = 0; u < 4; u++) {
        h[u] = __float2bfloat16(vs[u]);
        l[u] = __float2bfloat16(vs[u] - __bfloat162float(h[u]));
    }
    ((__nv_bfloat162*)hi)[i * 2 + 0] = __nv_bfloat162(h[0], h[1]);
    ((__nv_bfloat162*)hi)[i * 2 + 1] = __nv_bfloat162(h[2], h[3]);
    ((__nv_bfloat162*)lo)[i * 2 + 0] = __nv_bfloat162(l[0], l[1]);
    ((__nv_bfloat162*)lo)[i * 2 + 1] = __nv_bfloat162(l[2], l[3]);
}

// ---------------------------------------------------------------------------
// Transpose + split: W[K][N] fp32 -> T_hi/T_lo[N][K] bf16
// ---------------------------------------------------------------------------
__global__ void transpose_split_kernel(const float* __restrict__ W,
                                       __nv_bfloat16* __restrict__ th,
                                       __nv_bfloat16* __restrict__ tl,
                                       int K, int N) {
    __shared__ float t[32][33];
    int k0 = blockIdx.y * 32, n0 = blockIdx.x * 32;
    for (int r = threadIdx.y; r < 32; r += 8)
        t[r][threadIdx.x] = W[(size_t)(k0 + r) * N + n0 + threadIdx.x];
    __syncthreads();
    for (int r = threadIdx.y; r < 32; r += 8) {
        float v = t[threadIdx.x][r];                 // = W[k0+tx][n0+r]
        __nv_bfloat16 h = __float2bfloat16(v);
        __nv_bfloat16 l = __float2bfloat16(v - __bfloat162float(h));
        size_t o = (size_t)(n0 + r) * K + k0 + threadIdx.x;
        th[o] = h;
        tl[o] = l;
    }
}

// ---------------------------------------------------------------------------
// mma.sync split-bf16 GEMM:  C[M,N] = A[M,K] @ Bt[N,K]^T   (fp32-accurate)
// CTA: 128x128 tile, BK=32, 8 warps, warp tile 32x64.
// 3 terms per k-chunk: AhBh + AhBl + AlBh.
// smem rows padded to 40 bf16 (80B) -> conflict-free ldmatrix.
// ---------------------------------------------------------------------------
#define ASTR 40
#define TILE_BF16 (128 * ASTR)          /* 5120 bf16 = 10240 B per tile */

__global__ __launch_bounds__(256, 2) void gemm_mma_kernel(
    const __nv_bfloat16* __restrict__ Ah, const __nv_bfloat16* __restrict__ Al,
    const __nv_bfloat16* __restrict__ Bh, const __nv_bfloat16* __restrict__ Bl,
    float* __restrict__ C, int N, int K)
{
    __shared__ __nv_bfloat16 sm[4 * TILE_BF16];   // Ah | Al | Bh | Bl

    const int tid = threadIdx.x;
    const int wid = tid >> 5, lid = tid & 31;
    const int wm = (wid & 3) * 32;       // warp m offset in tile
    const int wn = (wid >> 2) * 64;      // warp n offset in tile

    const size_t aoff0 = (size_t)blockIdx.y * 128 * K;
    const size_t boff0 = (size_t)blockIdx.x * 128 * K;

    const uint32_t sbase = smem_u32(sm);

    // per-lane ldmatrix base addresses (byte offsets within a tile)
    // A fragment (m16k16): row = wm + mt*16 + (l&7) + ((l>>3)&1)*8, kcol = (l>>4)*8
    uint32_t aAddr[2];
#pragma unroll
    for (int mt = 0; mt < 2; mt++)
        aAddr[mt] = ((wm + mt * 16 + (lid & 7) + ((lid >> 3) & 1) * 8) * ASTR
                     + (lid >> 4) * 8) * 2;
    // B fragment (two n8 tiles x k16): row = wn + p*16 + (l&7) + (l>>4)*8,
    //                                  kcol = ((l>>3)&1)*8
    uint32_t bAddr[4];
#pragma unroll
    for (int p = 0; p < 4; p++)
        bAddr[p] = ((wn + p * 16 + (lid & 7) + (lid >> 4) * 8) * ASTR
                    + ((lid >> 3) & 1) * 8) * 2;

    const uint32_t sAh = sbase;
    const uint32_t sAl = sbase + TILE_BF16 * 2;
    const uint32_t sBh = sbase + 2 * TILE_BF16 * 2;
    const uint32_t sBl = sbase + 3 * TILE_BF16 * 2;

    float acc[2][8][4] = {};

    const int nchunks = K >> 5;
    for (int c = 0; c < nchunks; c++) {
        const int k0 = c * 32;
        // load 4 tiles (128x32 bf16 each), vectorized 16B
        {
            const __nv_bfloat16* srcs[4] = {
                Ah + aoff0 + k0, Al + aoff0 + k0,
                Bh + boff0 + k0, Bl + boff0 + k0 };
#pragma unroll
            for (int tI = 0; tI < 4; tI++) {
                __nv_bfloat16* dst = sm + tI * TILE_BF16;
                const __nv_bfloat16* src = srcs[tI];
#pragma unroll
                for (int it = 0; it < 2; it++) {
                    int idx = tid + it * 256;
                    int row = idx >> 2, kc = (idx & 3) * 8;
                    *(uint4*)&dst[row * ASTR + kc] =
                        *(const uint4*)(src + (size_t)row * K + kc);
                }
            }
        }
        __syncthreads();

#pragma unroll
        for (int ks = 0; ks < 2; ks++) {
            const uint32_t kb = ks * 32;   // 16 bf16 = 32 bytes
            uint32_t ah[2][4], al[2][4];
#pragma unroll
            for (int mt = 0; mt < 2; mt++) {
                LDSM_X4(ah[mt], sAh + aAddr[mt] + kb);
                LDSM_X4(al[mt], sAl + aAddr[mt] + kb);
            }
#pragma unroll
            for (int p = 0; p < 4; p++) {
                uint32_t bh[4], bl[4];
                LDSM_X4(bh, sBh + bAddr[p] + kb);
                LDSM_X4(bl, sBl + bAddr[p] + kb);
#pragma unroll
                for (int mt = 0; mt < 2; mt++) {
                    MMA16816(acc[mt][2 * p],     ah[mt], bh);
                    MMA16816(acc[mt][2 * p],     ah[mt], bl);
                    MMA16816(acc[mt][2 * p],     al[mt], bh);
                    MMA16816(acc[mt][2 * p + 1], ah[mt], bh + 2);
                    MMA16816(acc[mt][2 * p + 1], ah[mt], bl + 2);
                    MMA16816(acc[mt][2 * p + 1], al[mt], bh + 2);
                }
            }
        }
        __syncthreads();
    }

    // epilogue: c0,c1 at (row = l>>2, col = 2*(l&3)); c2,c3 at row+8
    const int mbase = blockIdx.y * 128 + wm + (lid >> 2);
    const int nbase = blockIdx.x * 128 + wn + (lid & 3) * 2;
#pragma unroll
    for (int mt = 0; mt < 2; mt++) {
#pragma unroll
        for (int nt = 0; nt < 8; nt++) {
            float* p0 = C + (size_t)(mbase + mt * 16) * N + nbase + nt * 8;
            float* p1 = C + (size_t)(mbase + mt * 16 + 8) * N + nbase + nt * 8;
            *(float2*)p0 = make_float2(acc[mt][nt][0], acc[mt][nt][1]);
            *(float2*)p1 = make_float2(acc[mt][nt][2], acc[mt][nt][3]);
        }
    }
}

// ---------------------------------------------------------------------------
// RoPE in-place on q (cols [0,1024)) and k (cols [1024,2048)) of g_qkv.
// ---------------------------------------------------------------------------
__global__ void rope_apply_kernel(float* __restrict__ qkv) {
    int idx = blockIdx.x * blockDim.x + threadIdx.x;
    if (idx >= M_ROWS * 1024) return;
    int row = idx >> 10;
    int p = idx & 1023;
    int col = ((p >> 9) << 10) + ((p & 511) << 1);
    int t = row & (T_SEQ - 1);
    int j = col & 63;
    int m0 = j & 31;

    float* ptr = qkv + (size_t)row * QKV_LD + col;
    float x0 = ptr[0], x1 = ptr[1];
    const float* ct = g_cos + t * 32;
    const float* st = g_sin + t * 32;
    ptr[0] = x0 * ct[m0] - x1 * st[m0];
    ptr[1] = x1 * ct[m0 + 1] + x0 * st[m0 + 1];
}

// ---------------------------------------------------------------------------
// Flash attention fp32 (SIMT). stride 68 keeps rows 16B aligned -> LDS.128.
// ---------------------------------------------------------------------------
#define AT_STR 68

__global__ __launch_bounds__(256) void attn64_kernel(
    const float* __restrict__ qkv, float* __restrict__ ao)
{
    extern __shared__ float smf[];
    float* Qs = smf;                   // [64 j][64 r] stride 68
    float* Ks = smf + 64 * AT_STR;     // [64 j][64 c] stride 68 (reused for P)
    float* Vs = smf + 2 * 64 * AT_STR; // [64 c][64 d] stride 68

    const int tid = threadIdx.x;
    const int b = blockIdx.y >> 4, h = blockIdx.y & 15;
    const int q0 = blockIdx.x * 64;
    const float* base = qkv + (size_t)b * T_SEQ * QKV_LD + h * 64;

    for (int idx = tid; idx < 1024; idx += 256) {
        int j4 = (idx >> 6) << 2, r = idx & 63;
        float4 v = *(const float4*)(base + (size_t)(q0 + r) * QKV_LD + j4);
        Qs[(j4 + 0) * AT_STR + r] = v.x * 0.125f;
        Qs[(j4 + 1) * AT_STR + r] = v.y * 0.125f;
        Qs[(j4 + 2) * AT_STR + r] = v.z * 0.125f;
        Qs[(j4 + 3) * AT_STR + r] = v.w * 0.125f;
    }

    const int ty = tid >> 4, tx = tid & 15;
    float o[4][4] = {};
    float mM[4] = {-INFINITY, -INFINITY, -INFINITY, -INFINITY};
    float lL[4] = {0.f, 0.f, 0.f, 0.f};
    __syncthreads();

    for (int s0 = 0; s0 < T_SEQ; s0 += 64) {
        for (int idx = tid; idx < 1024; idx += 256) {
            int j4 = (idx >> 6) << 2, c = idx & 63;
            float4 kv = *(const float4*)(base + (size_t)(s0 + c) * QKV_LD + 1024 + j4);
            Ks[(j4 + 0) * AT_STR + c] = kv.x;
            Ks[(j4 + 1) * AT_STR + c] = kv.y;
            Ks[(j4 + 2) * AT_STR + c] = kv.z;
            Ks[(j4 + 3) * AT_STR + c] = kv.w;
        }
        for (int idx = tid; idx < 1024; idx += 256) {
            int c = idx >> 4, j4 = (idx & 15) << 2;
            *(float4*)&Vs[c * AT_STR + j4] =
                *(const float4*)(base + (size_t)(s0 + c) * QKV_LD + 2048 + j4);
        }
        __syncthreads();

        float sc[4][4] = {};
#pragma unroll 8
        for (int j = 0; j < 64; j++) {
            float4 q4 = *(const float4*)&Qs[j * AT_STR + ty * 4];
            float4 k4 = *(const float4*)&Ks[j * AT_STR + tx * 4];
            float qr[4] = {q4.x, q4.y, q4.z, q4.w};
            float kc[4] = {k4.x, k4.y, k4.z, k4.w};
#pragma unroll
            for (int i = 0; i < 4; i++)
#pragma unroll
                for (int c = 0; c < 4; c++)
                    sc[i][c] += qr[i] * kc[c];
        }
        __syncthreads();

#pragma unroll
        for (int i = 0; i < 4; i++) {
            float mx = fmaxf(fmaxf(sc[i][0], sc[i][1]), fmaxf(sc[i][2], sc[i][3]));
#pragma unroll
            for (int off = 8; off >= 1; off >>= 1)
                mx = fmaxf(mx, __shfl_xor_sync(0xffffffffu, mx, off));
            float mnew = fmaxf(mM[i], mx);
            float alpha = __expf(mM[i] - mnew);
            float rs = 0.f;
#pragma unroll
            for (int c = 0; c < 4; c++) {
                sc[i][c] = __expf(sc[i][c] - mnew);
                rs += sc[i][c];
            }
#pragma unroll
            for (int off = 8; off >= 1; off >>= 1)
                rs += __shfl_xor_sync(0xffffffffu, rs, off);
            lL[i] = lL[i] * alpha + rs;
            mM[i] = mnew;
#pragma unroll
            for (int d = 0; d < 4; d++) o[i][d] *= alpha;
        }

#pragma unroll
        for (int c = 0; c < 4; c++)
            *(float4*)&Ks[(tx * 4 + c) * AT_STR + ty * 4] =
                make_float4(sc[0][c], sc[1][c], sc[2][c], sc[3][c]);
        __syncthreads();

#pragma unroll 8
        for (int cc = 0; cc < 64; cc++) {
            float4 p4 = *(const float4*)&Ks[cc * AT_STR + ty * 4];
            float4 v4 = *(const float4*)&Vs[cc * AT_STR + tx * 4];
            float pr[4] = {p4.x, p4.y, p4.z, p4.w};
            float vv[4] = {v4.x, v4.y, v4.z, v4.w};
#pragma unroll
            for (int i = 0; i < 4; i++)
#pragma unroll
                for (int d = 0; d < 4; d++)
                    o[i][d] += pr[i] * vv[d];
        }
        __syncthreads();
    }

#pragma unroll
    for (int i = 0; i < 4; i++) {
        float inv = 1.0f / lL[i];
        *(float4*)(ao + (size_t)(b * T_SEQ + q0 + ty * 4 + i) * D_MODEL + h * 64 + tx * 4)
            = make_float4(o[i][0] * inv, o[i][1] * inv, o[i][2] * inv, o[i][3] * inv);
    }
}

// ---------------------------------------------------------------------------
// Launch
// ---------------------------------------------------------------------------
extern "C" void kernel_launch(void* const* d_in, const int* in_sizes, int n_in,
                              void* d_out, int out_size) {
    const float* x    = (const float*)d_in[0];
    const float* Wqkv = (const float*)d_in[1];
    const float* Wout = (const float*)d_in[2];
    float* out = (float*)d_out;

    float *qkv, *ao;
    __nv_bfloat16 *xhi, *xlo, *aohi, *aolo, *wqh, *wql, *woh, *wol;
    cudaGetSymbolAddress((void**)&qkv, g_qkv);
    cudaGetSymbolAddress((void**)&ao, g_ao);
    cudaGetSymbolAddress((void**)&xhi, g_xhi);
    cudaGetSymbolAddress((void**)&xlo, g_xlo);
    cudaGetSymbolAddress((void**)&aohi, g_aohi);
    cudaGetSymbolAddress((void**)&aolo, g_aolo);
    cudaGetSymbolAddress((void**)&wqh, g_wqt_hi);
    cudaGetSymbolAddress((void**)&wql, g_wqt_lo);
    cudaGetSymbolAddress((void**)&woh, g_wot_hi);
    cudaGetSymbolAddress((void**)&wol, g_wot_lo);

    const int at_smem = 3 * 64 * AT_STR * (int)sizeof(float);
    cudaFuncSetAttribute(attn64_kernel,
                         cudaFuncAttributeMaxDynamicSharedMemorySize, at_smem);

    // 1. RoPE tables
    gen_tables_kernel<<<(T_SEQ * 32 + 255) / 256, 256>>>();

    // 2. Prepare operands: split x, transpose+split weights
    split_kernel<<<(M_ROWS * D_MODEL / 4 + 255) / 256, 256>>>(x, xhi, xlo, M_ROWS * D_MODEL / 4);
    transpose_split_kernel<<<dim3(QKV_LD / 32, D_MODEL / 32), dim3(32, 8)>>>(Wqkv, wqh, wql, D_MODEL, QKV_LD);
    transpose_split_kernel<<<dim3(D_MODEL / 32, D_MODEL / 32), dim3(32, 8)>>>(Wout, woh, wol, D_MODEL, D_MODEL);

    // 3. QKV projection (mma.sync): qkv[4096,3072] = x @ Wqkv
    gemm_mma_kernel<<<dim3(QKV_LD / 128, M_ROWS / 128), 256>>>(
        xhi, xlo, wqh, wql, qkv, QKV_LD, D_MODEL);

    // 4. RoPE in-place on q,k
    rope_apply_kernel<<<(M_ROWS * 1024) / 256, 256>>>(qkv);

    // 5. Attention
    attn64_kernel<<<dim3(T_SEQ / 64, B_BATCH * H_HEADS), 256, at_smem>>>(qkv, ao);

    // 6. Split attention output, output projection (mma.sync)
    split_kernel<<<(M_ROWS * D_MODEL / 4 + 255) / 256, 256>>>(ao, aohi, aolo, M_ROWS * D_MODEL / 4);
    gemm_mma_kernel<<<dim3(D_MODEL / 128, M_ROWS / 128), 256>>>(
        aohi, aolo, woh, wol, out, D_MODEL, D_MODEL);
}

// round 4
// speedup vs baseline: 2.9340x; 2.0149x over previous
#include <cuda_runtime.h>
#include <cuda_bf16.h>
#include <math.h>
#include <stdint.h>

#define T_SEQ 2048
#define B_BATCH 2
#define D_MODEL 1024
#define H_HEADS 16
#define M_ROWS 4096          /* B*T */
#define QKV_LD 3072

// ---------------------------------------------------------------------------
// Scratch (static __device__ — no allocations allowed anywhere)
// ---------------------------------------------------------------------------
__device__ __nv_bfloat16 g_qkvh[(size_t)M_ROWS * QKV_LD];   // 25 MB (rope+scale applied)
__device__ __nv_bfloat16 g_qkvl[(size_t)M_ROWS * QKV_LD];
__device__ __nv_bfloat16 g_xhi[(size_t)M_ROWS * D_MODEL];
__device__ __nv_bfloat16 g_xlo[(size_t)M_ROWS * D_MODEL];
__device__ __nv_bfloat16 g_aohi[(size_t)M_ROWS * D_MODEL];
__device__ __nv_bfloat16 g_aolo[(size_t)M_ROWS * D_MODEL];
__device__ __nv_bfloat16 g_wqt_hi[(size_t)QKV_LD * D_MODEL];   // Wqkv^T [3072,1024]
__device__ __nv_bfloat16 g_wqt_lo[(size_t)QKV_LD * D_MODEL];
__device__ __nv_bfloat16 g_wot_hi[(size_t)D_MODEL * D_MODEL];  // Wout^T [1024,1024]
__device__ __nv_bfloat16 g_wot_lo[(size_t)D_MODEL * D_MODEL];
__device__ float g_cos[T_SEQ * 32];
__device__ float g_sin[T_SEQ * 32];

// ---------------------------------------------------------------------------
// Helpers
// ---------------------------------------------------------------------------
__device__ __forceinline__ uint32_t smem_u32(const void* p) {
    uint32_t a;
    asm("{ .reg .u64 t; cvta.to.shared.u64 t, %1; cvt.u32.u64 %0, t; }"
        : "=r"(a) : "l"(p));
    return a;
}

#define LDSM_X4(r, addr)                                                     \
    asm volatile("ldmatrix.sync.aligned.m8n8.x4.shared.b16 {%0,%1,%2,%3}, [%4];" \
        : "=r"((r)[0]), "=r"((r)[1]), "=r"((r)[2]), "=r"((r)[3])             \
        : "r"(addr))

#define LDSM_X4_T(r, addr)                                                   \
    asm volatile("ldmatrix.sync.aligned.m8n8.x4.trans.shared.b16 {%0,%1,%2,%3}, [%4];" \
        : "=r"((r)[0]), "=r"((r)[1]), "=r"((r)[2]), "=r"((r)[3])             \
        : "r"(addr))

#define MMA16816(c, a, b)                                                    \
    asm volatile("mma.sync.aligned.m16n8k16.row.col.f32.bf16.bf16.f32 "      \
        "{%0,%1,%2,%3}, {%4,%5,%6,%7}, {%8,%9}, {%0,%1,%2,%3};"              \
        : "+f"((c)[0]), "+f"((c)[1]), "+f"((c)[2]), "+f"((c)[3])             \
        : "r"((a)[0]), "r"((a)[1]), "r"((a)[2]), "r"((a)[3]),                \
          "r"((b)[0]), "r"((b)[1]))

__device__ __forceinline__ uint32_t packbf(float a, float b) {
    __nv_bfloat162 t(__float2bfloat16(a), __float2bfloat16(b));
    return *(uint32_t*)&t;
}
__device__ __forceinline__ void split2(float a, float b, uint32_t& hi, uint32_t& lo) {
    __nv_bfloat16 ha = __float2bfloat16(a), hb = __float2bfloat16(b);
    __nv_bfloat16 la = __float2bfloat16(a - __bfloat162float(ha));
    __nv_bfloat16 lb = __float2bfloat16(b - __bfloat162float(hb));
    __nv_bfloat162 th(ha, hb), tl(la, lb);
    hi = *(uint32_t*)&th;
    lo = *(uint32_t*)&tl;
}

// ---------------------------------------------------------------------------
// RoPE tables (fp64 phase for accuracy)
// ---------------------------------------------------------------------------
__global__ void gen_tables_kernel() {
    int i = blockIdx.x * blockDim.x + threadIdx.x;
    if (i >= T_SEQ * 32) return;
    int t = i >> 5, m = i & 31;
    double invf = exp(-(double)(2 * m) * (log(10000.0) / 64.0));
    double ph = (double)t * invf;
    g_cos[i] = (float)cos(ph);
    g_sin[i] = (float)sin(ph);
}

// ---------------------------------------------------------------------------
// Split fp32 -> (hi, lo) bf16 (x only)
// ---------------------------------------------------------------------------
__global__ void split_kernel(const float* __restrict__ in,
                             __nv_bfloat16* __restrict__ hi,
                             __nv_bfloat16* __restrict__ lo, int n4) {
    int i = blockIdx.x * blockDim.x + threadIdx.x;
    if (i >= n4) return;
    float4 v = ((const float4*)in)[i];
    uint32_t h0, l0, h1, l1;
    split2(v.x, v.y, h0, l0);
    split2(v.z, v.w, h1, l1);
    ((uint32_t*)hi)[i * 2 + 0] = h0;
    ((uint32_t*)hi)[i * 2 + 1] = h1;
    ((uint32_t*)lo)[i * 2 + 0] = l0;
    ((uint32_t*)lo)[i * 2 + 1] = l1;
}

// ---------------------------------------------------------------------------
// Transpose + split: W[K][N] fp32 -> T_hi/T_lo[N][K] bf16
// ---------------------------------------------------------------------------
__global__ void transpose_split_kernel(const float* __restrict__ W,
                                       __nv_bfloat16* __restrict__ th,
                                       __nv_bfloat16* __restrict__ tl,
                                       int K, int N) {
    __shared__ float t[32][33];
    int k0 = blockIdx.y * 32, n0 = blockIdx.x * 32;
    for (int r = threadIdx.y; r < 32; r += 8)
        t[r][threadIdx.x] = W[(size_t)(k0 + r) * N + n0 + threadIdx.x];
    __syncthreads();
    for (int r = threadIdx.y; r < 32; r += 8) {
        float v = t[threadIdx.x][r];
        __nv_bfloat16 h = __float2bfloat16(v);
        __nv_bfloat16 l = __float2bfloat16(v - __bfloat162float(h));
        size_t o = (size_t)(n0 + r) * K + k0 + threadIdx.x;
        th[o] = h;
        tl[o] = l;
    }
}

// ---------------------------------------------------------------------------
// mma.sync split-bf16 GEMM:  C = A[M,K] @ Bt[N,K]^T
// EPI=0: write fp32 C.   EPI=1: apply RoPE (+0.125 Q scale) and write split
// bf16 hi/lo (the QKV path).
// ---------------------------------------------------------------------------
#define ASTR 40
#define TILE_BF16 (128 * ASTR)

template <int EPI>
__global__ __launch_bounds__(256, 2) void gemm_mma_kernel(
    const __nv_bfloat16* __restrict__ Ah, const __nv_bfloat16* __restrict__ Al,
    const __nv_bfloat16* __restrict__ Bh, const __nv_bfloat16* __restrict__ Bl,
    float* __restrict__ C, __nv_bfloat16* __restrict__ Ch,
    __nv_bfloat16* __restrict__ Cl, int N, int K)
{
    __shared__ __nv_bfloat16 sm[4 * TILE_BF16];

    const int tid = threadIdx.x;
    const int wid = tid >> 5, lid = tid & 31;
    const int wm = (wid & 3) * 32;
    const int wn = (wid >> 2) * 64;

    const size_t aoff0 = (size_t)blockIdx.y * 128 * K;
    const size_t boff0 = (size_t)blockIdx.x * 128 * K;

    const uint32_t sbase = smem_u32(sm);

    uint32_t aAddr[2];
#pragma unroll
    for (int mt = 0; mt < 2; mt++)
        aAddr[mt] = ((wm + mt * 16 + (lid & 15)) * ASTR + (lid >> 4) * 8) * 2;
    uint32_t bAddr[4];
#pragma unroll
    for (int p = 0; p < 4; p++)
        bAddr[p] = ((wn + p * 16 + (lid & 7) + (lid >> 4) * 8) * ASTR
                    + ((lid >> 3) & 1) * 8) * 2;

    const uint32_t sAh = sbase;
    const uint32_t sAl = sbase + TILE_BF16 * 2;
    const uint32_t sBh = sbase + 2 * TILE_BF16 * 2;
    const uint32_t sBl = sbase + 3 * TILE_BF16 * 2;

    float acc[2][8][4] = {};

    const int nchunks = K >> 5;
    for (int c = 0; c < nchunks; c++) {
        const int k0 = c * 32;
        {
            const __nv_bfloat16* srcs[4] = {
                Ah + aoff0 + k0, Al + aoff0 + k0,
                Bh + boff0 + k0, Bl + boff0 + k0 };
#pragma unroll
            for (int tI = 0; tI < 4; tI++) {
                __nv_bfloat16* dst = sm + tI * TILE_BF16;
                const __nv_bfloat16* src = srcs[tI];
#pragma unroll
                for (int it = 0; it < 2; it++) {
                    int idx = tid + it * 256;
                    int row = idx >> 2, kc = (idx & 3) * 8;
                    *(uint4*)&dst[row * ASTR + kc] =
                        *(const uint4*)(src + (size_t)row * K + kc);
                }
            }
        }
        __syncthreads();

#pragma unroll
        for (int ks = 0; ks < 2; ks++) {
            const uint32_t kb = ks * 32;
            uint32_t ah[2][4], al[2][4];
#pragma unroll
            for (int mt = 0; mt < 2; mt++) {
                LDSM_X4(ah[mt], sAh + aAddr[mt] + kb);
                LDSM_X4(al[mt], sAl + aAddr[mt] + kb);
            }
#pragma unroll
            for (int p = 0; p < 4; p++) {
                uint32_t bh[4], bl[4];
                LDSM_X4(bh, sBh + bAddr[p] + kb);
                LDSM_X4(bl, sBl + bAddr[p] + kb);
#pragma unroll
                for (int mt = 0; mt < 2; mt++) {
                    MMA16816(acc[mt][2 * p],     ah[mt], bh);
                    MMA16816(acc[mt][2 * p],     ah[mt], bl);
                    MMA16816(acc[mt][2 * p],     al[mt], bh);
                    MMA16816(acc[mt][2 * p + 1], ah[mt], bh + 2);
                    MMA16816(acc[mt][2 * p + 1], ah[mt], bl + 2);
                    MMA16816(acc[mt][2 * p + 1], al[mt], bh + 2);
                }
            }
        }
        __syncthreads();
    }

    const int mbase = blockIdx.y * 128 + wm + (lid >> 2);
    const int nbase = blockIdx.x * 128 + wn + (lid & 3) * 2;
#pragma unroll
    for (int mt = 0; mt < 2; mt++) {
#pragma unroll
        for (int half = 0; half < 2; half++) {
            const int row = mbase + mt * 16 + half * 8;
#pragma unroll
            for (int nt = 0; nt < 8; nt++) {
                const int col = nbase + nt * 8;
                float v0 = acc[mt][nt][2 * half + 0];
                float v1 = acc[mt][nt][2 * half + 1];
                if (EPI == 0) {
                    *(float2*)(C + (size_t)row * N + col) = make_float2(v0, v1);
                } else {
                    if (col < 2048) {                     // rope on q,k
                        int t = row & (T_SEQ - 1);
                        int m0 = col & 31;                 // even
                        float c0 = g_cos[t * 32 + m0], s0 = g_sin[t * 32 + m0];
                        float c1 = g_cos[t * 32 + m0 + 1], s1 = g_sin[t * 32 + m0 + 1];
                        float o0 = v0 * c0 - v1 * s0;
                        float o1 = v1 * c1 + v0 * s1;
                        if (col < 1024) { o0 *= 0.125f; o1 *= 0.125f; }  // q scale
                        v0 = o0; v1 = o1;
                    }
                    uint32_t hi, lo;
                    split2(v0, v1, hi, lo);
                    *(uint32_t*)(Ch + (size_t)row * N + col) = hi;
                    *(uint32_t*)(Cl + (size_t)row * N + col) = lo;
                }
            }
        }
    }
}

// ---------------------------------------------------------------------------
// mma.sync flash attention, split-bf16 (3-term) for S and PV.
// CTA: 128 q-rows x one (b,h). 8 warps x m16. K/V chunks of 64.
// smem stride 72 bf16 (144B) -> conflict-free ldmatrix.
// ---------------------------------------------------------------------------
#define QSTR 72
#define AH_OFF 0
#define AL_OFF (128 * QSTR)
#define KH_OFF (2 * 128 * QSTR)
#define KVT (64 * QSTR)
#define ATT_SMEM ((2 * 128 * QSTR + 4 * 64 * QSTR) * 2)   /* 73728 B */

__global__ __launch_bounds__(256, 2) void attn_mma_kernel(
    const __nv_bfloat16* __restrict__ qh, const __nv_bfloat16* __restrict__ ql,
    __nv_bfloat16* __restrict__ aoh, __nv_bfloat16* __restrict__ aol)
{
    extern __shared__ __nv_bfloat16 sma[];
    const int tid = threadIdx.x, wid = tid >> 5, lid = tid & 31;
    const int b = blockIdx.y >> 4, h = blockIdx.y & 15;
    const int q0 = blockIdx.x * 128;
    const size_t rowbase = (size_t)(b * T_SEQ) * QKV_LD;
    const int hc = h * 64;

    // Load resident Q tiles (hi/lo), 128x64 each
#pragma unroll
    for (int i = 0; i < 4; i++) {
        int idx = tid + i * 256;                 // 0..1023
        int r = idx >> 3, c8 = (idx & 7) * 8;
        size_t g = rowbase + (size_t)(q0 + r) * QKV_LD + hc + c8;
        *(uint4*)&sma[AH_OFF + r * QSTR + c8] = *(const uint4*)(qh + g);
        *(uint4*)&sma[AL_OFF + r * QSTR + c8] = *(const uint4*)(ql + g);
    }

    const uint32_t sb = smem_u32(sma);
    const int wm = wid * 16;
    const uint32_t qAddr = sb + ((wm + (lid & 15)) * QSTR + (lid >> 4) * 8) * 2;
    const uint32_t kAddr = sb + KH_OFF * 2 +
        (((lid & 7) + (lid >> 4) * 8) * QSTR + ((lid >> 3) & 1) * 8) * 2;
    const uint32_t vAddr = sb + (KH_OFF + 2 * KVT) * 2 +
        ((lid & 15) * QSTR + (lid >> 4) * 8) * 2;

    float o[8][4] = {};
    float mrow[2] = {-INFINITY, -INFINITY};
    float lrow[2] = {0.f, 0.f};

    for (int s0 = 0; s0 < T_SEQ; s0 += 64) {
        __syncthreads();
        // Load K,V hi/lo chunk tiles (64x64 each)
#pragma unroll
        for (int i = 0; i < 2; i++) {
            int idx = tid + i * 256;             // 0..511
            int r = idx >> 3, c8 = (idx & 7) * 8;
            size_t gk = rowbase + (size_t)(s0 + r) * QKV_LD + 1024 + hc + c8;
            size_t gv = gk + 1024;
            int so = r * QSTR + c8;
            *(uint4*)&sma[KH_OFF + so]           = *(const uint4*)(qh + gk);
            *(uint4*)&sma[KH_OFF + KVT + so]     = *(const uint4*)(ql + gk);
            *(uint4*)&sma[KH_OFF + 2 * KVT + so] = *(const uint4*)(qh + gv);
            *(uint4*)&sma[KH_OFF + 3 * KVT + so] = *(const uint4*)(ql + gv);
        }
        __syncthreads();

        // S = Q K^T  (3-term split)
        float sc[8][4] = {};
#pragma unroll
        for (int ks = 0; ks < 4; ks++) {
            uint32_t ah[4], al[4];
            LDSM_X4(ah, qAddr + ks * 32);
            LDSM_X4(al, qAddr + AL_OFF * 2 + ks * 32);
#pragma unroll
            for (int p = 0; p < 4; p++) {
                uint32_t bh[4], bl[4];
                uint32_t ka = kAddr + p * (16 * QSTR * 2) + ks * 32;
                LDSM_X4(bh, ka);
                LDSM_X4(bl, ka + KVT * 2);
                MMA16816(sc[2 * p],     ah, bh);
                MMA16816(sc[2 * p],     ah, bl);
                MMA16816(sc[2 * p],     al, bh);
                MMA16816(sc[2 * p + 1], ah, bh + 2);
                MMA16816(sc[2 * p + 1], ah, bl + 2);
                MMA16816(sc[2 * p + 1], al, bh + 2);
            }
        }

        // Online softmax (two rows per thread: r1 = lid>>2, r2 = r1+8)
#pragma unroll
        for (int hr = 0; hr < 2; hr++) {
            float mx = -INFINITY;
#pragma unroll
            for (int t = 0; t < 8; t++)
                mx = fmaxf(mx, fmaxf(sc[t][2 * hr], sc[t][2 * hr + 1]));
            mx = fmaxf(mx, __shfl_xor_sync(0xffffffffu, mx, 1));
            mx = fmaxf(mx, __shfl_xor_sync(0xffffffffu, mx, 2));
            float mnew = fmaxf(mrow[hr], mx);
            float alpha = __expf(mrow[hr] - mnew);
            float rs = 0.f;
#pragma unroll
            for (int t = 0; t < 8; t++) {
                float e0 = __expf(sc[t][2 * hr] - mnew);
                float e1 = __expf(sc[t][2 * hr + 1] - mnew);
                sc[t][2 * hr] = e0;
                sc[t][2 * hr + 1] = e1;
                rs += e0 + e1;
            }
            rs += __shfl_xor_sync(0xffffffffu, rs, 1);
            rs += __shfl_xor_sync(0xffffffffu, rs, 2);
            lrow[hr] = lrow[hr] * alpha + rs;
            mrow[hr] = mnew;
#pragma unroll
            for (int t = 0; t < 8; t++) {
                o[t][2 * hr] *= alpha;
                o[t][2 * hr + 1] *= alpha;
            }
        }

        // Convert P to split bf16 A-fragments (registers line up with S tiles)
        uint32_t ph[4][4], pl[4][4];
#pragma unroll
        for (int ks = 0; ks < 4; ks++) {
            split2(sc[2 * ks][0],     sc[2 * ks][1],     ph[ks][0], pl[ks][0]);
            split2(sc[2 * ks][2],     sc[2 * ks][3],     ph[ks][1], pl[ks][1]);
            split2(sc[2 * ks + 1][0], sc[2 * ks + 1][1], ph[ks][2], pl[ks][2]);
            split2(sc[2 * ks + 1][2], sc[2 * ks + 1][3], ph[ks][3], pl[ks][3]);
        }

        // O += P V  (V via ldmatrix.trans; 3-term split)
#pragma unroll
        for (int ks = 0; ks < 4; ks++) {
#pragma unroll
            for (int p = 0; p < 4; p++) {
                uint32_t vh[4], vl[4];
                uint32_t va = vAddr + ks * (16 * QSTR * 2) + p * 32;
                LDSM_X4_T(vh, va);
                LDSM_X4_T(vl, va + KVT * 2);
                MMA16816(o[2 * p],     ph[ks], vh);
                MMA16816(o[2 * p],     ph[ks], vl);
                MMA16816(o[2 * p],     pl[ks], vh);
                MMA16816(o[2 * p + 1], ph[ks], vh + 2);
                MMA16816(o[2 * p + 1], ph[ks], vl + 2);
                MMA16816(o[2 * p + 1], pl[ks], vh + 2);
            }
        }
    }

    // Normalize + split-store to aoh/aol  [B*T, 1024] at col h*64+...
#pragma unroll
    for (int hr = 0; hr < 2; hr++) {
        int r = q0 + wm + (lid >> 2) + hr * 8;
        float inv = 1.0f / lrow[hr];
        size_t rowoff = (size_t)(b * T_SEQ + r) * D_MODEL + hc + (lid & 3) * 2;
#pragma unroll
        for (int t = 0; t < 8; t++) {
            float v0 = o[t][2 * hr] * inv;
            float v1 = o[t][2 * hr + 1] * inv;
            uint32_t hi, lo;
            split2(v0, v1, hi, lo);
            *(uint32_t*)(aoh + rowoff + t * 8) = hi;
            *(uint32_t*)(aol + rowoff + t * 8) = lo;
        }
    }
}

// ---------------------------------------------------------------------------
// Launch
// ---------------------------------------------------------------------------
extern "C" void kernel_launch(void* const* d_in, const int* in_sizes, int n_in,
                              void* d_out, int out_size) {
    const float* x    = (const float*)d_in[0];
    const float* Wqkv = (const float*)d_in[1];
    const float* Wout = (const float*)d_in[2];
    float* out = (float*)d_out;

    __nv_bfloat16 *qkvh, *qkvl, *xhi, *xlo, *aohi, *aolo, *wqh, *wql, *woh, *wol;
    cudaGetSymbolAddress((void**)&qkvh, g_qkvh);
    cudaGetSymbolAddress((void**)&qkvl, g_qkvl);
    cudaGetSymbolAddress((void**)&xhi, g_xhi);
    cudaGetSymbolAddress((void**)&xlo, g_xlo);
    cudaGetSymbolAddress((void**)&aohi, g_aohi);
    cudaGetSymbolAddress((void**)&aolo, g_aolo);
    cudaGetSymbolAddress((void**)&wqh, g_wqt_hi);
    cudaGetSymbolAddress((void**)&wql, g_wqt_lo);
    cudaGetSymbolAddress((void**)&woh, g_wot_hi);
    cudaGetSymbolAddress((void**)&wol, g_wot_lo);

    cudaFuncSetAttribute(attn_mma_kernel,
                         cudaFuncAttributeMaxDynamicSharedMemorySize, ATT_SMEM);

    // 1. RoPE tables
    gen_tables_kernel<<<(T_SEQ * 32 + 255) / 256, 256>>>();

    // 2. Prepare operands
    split_kernel<<<(M_ROWS * D_MODEL / 4 + 255) / 256, 256>>>(x, xhi, xlo, M_ROWS * D_MODEL / 4);
    transpose_split_kernel<<<dim3(QKV_LD / 32, D_MODEL / 32), dim3(32, 8)>>>(Wqkv, wqh, wql, D_MODEL, QKV_LD);
    transpose_split_kernel<<<dim3(D_MODEL / 32, D_MODEL / 32), dim3(32, 8)>>>(Wout, woh, wol, D_MODEL, D_MODEL);

    // 3. QKV projection + fused RoPE/scale/split epilogue
    gemm_mma_kernel<1><<<dim3(QKV_LD / 128, M_ROWS / 128), 256>>>(
        xhi, xlo, wqh, wql, nullptr, qkvh, qkvl, QKV_LD, D_MODEL);

    // 4. Attention (mma.sync flash, split-bf16)
    attn_mma_kernel<<<dim3(T_SEQ / 128, B_BATCH * H_HEADS), 256, ATT_SMEM>>>(
        qkvh, qkvl, aohi, aolo);

    // 5. Output projection
    gemm_mma_kernel<0><<<dim3(D_MODEL / 128, M_ROWS / 128), 256>>>(
        aohi, aolo, woh, wol, out, nullptr, nullptr, D_MODEL, D_MODEL);
}

// round 5
// speedup vs baseline: 2.9648x; 1.0105x over previous
#include <cuda_runtime.h>
#include <cuda_bf16.h>
#include <math.h>
#include <stdint.h>

#define T_SEQ 2048
#define B_BATCH 2
#define D_MODEL 1024
#define H_HEADS 16
#define M_ROWS 4096          /* B*T */
#define QKV_LD 3072

// ---------------------------------------------------------------------------
// Scratch (static __device__ — no allocations allowed anywhere)
// ---------------------------------------------------------------------------
__device__ __nv_bfloat16 g_qkvh[(size_t)M_ROWS * QKV_LD];   // rope+scale applied
__device__ __nv_bfloat16 g_qkvl[(size_t)M_ROWS * QKV_LD];
__device__ __nv_bfloat16 g_xhi[(size_t)M_ROWS * D_MODEL];
__device__ __nv_bfloat16 g_xlo[(size_t)M_ROWS * D_MODEL];
__device__ __nv_bfloat16 g_aohi[(size_t)M_ROWS * D_MODEL];
__device__ __nv_bfloat16 g_aolo[(size_t)M_ROWS * D_MODEL];
__device__ __nv_bfloat16 g_wqt_hi[(size_t)QKV_LD * D_MODEL];
__device__ __nv_bfloat16 g_wqt_lo[(size_t)QKV_LD * D_MODEL];
__device__ __nv_bfloat16 g_wot_hi[(size_t)D_MODEL * D_MODEL];
__device__ __nv_bfloat16 g_wot_lo[(size_t)D_MODEL * D_MODEL];
__device__ float g_cos[T_SEQ * 32];
__device__ float g_sin[T_SEQ * 32];

// ---------------------------------------------------------------------------
// Helpers
// ---------------------------------------------------------------------------
__device__ __forceinline__ uint32_t smem_u32(const void* p) {
    uint32_t a;
    asm("{ .reg .u64 t; cvta.to.shared.u64 t, %1; cvt.u32.u64 %0, t; }"
        : "=r"(a) : "l"(p));
    return a;
}

#define CP16(dst, src)                                                       \
    asm volatile("cp.async.cg.shared.global [%0], [%1], 16;"                 \
        :: "r"(dst), "l"(src))
#define CP_COMMIT() asm volatile("cp.async.commit_group;" ::: "memory")
#define CP_WAIT0()  asm volatile("cp.async.wait_group 0;" ::: "memory")
#define CP_WAIT1()  asm volatile("cp.async.wait_group 1;" ::: "memory")

#define LDSM_X4(r, addr)                                                     \
    asm volatile("ldmatrix.sync.aligned.m8n8.x4.shared.b16 {%0,%1,%2,%3}, [%4];" \
        : "=r"((r)[0]), "=r"((r)[1]), "=r"((r)[2]), "=r"((r)[3])             \
        : "r"(addr))

#define LDSM_X4_T(r, addr)                                                   \
    asm volatile("ldmatrix.sync.aligned.m8n8.x4.trans.shared.b16 {%0,%1,%2,%3}, [%4];" \
        : "=r"((r)[0]), "=r"((r)[1]), "=r"((r)[2]), "=r"((r)[3])             \
        : "r"(addr))

#define MMA16816(c, a, b)                                                    \
    asm volatile("mma.sync.aligned.m16n8k16.row.col.f32.bf16.bf16.f32 "      \
        "{%0,%1,%2,%3}, {%4,%5,%6,%7}, {%8,%9}, {%0,%1,%2,%3};"              \
        : "+f"((c)[0]), "+f"((c)[1]), "+f"((c)[2]), "+f"((c)[3])             \
        : "r"((a)[0]), "r"((a)[1]), "r"((a)[2]), "r"((a)[3]),                \
          "r"((b)[0]), "r"((b)[1]))

__device__ __forceinline__ void split2(float a, float b, uint32_t& hi, uint32_t& lo) {
    __nv_bfloat16 ha = __float2bfloat16(a), hb = __float2bfloat16(b);
    __nv_bfloat16 la = __float2bfloat16(a - __bfloat162float(ha));
    __nv_bfloat16 lb = __float2bfloat16(b - __bfloat162float(hb));
    __nv_bfloat162 th(ha, hb), tl(la, lb);
    hi = *(uint32_t*)&th;
    lo = *(uint32_t*)&tl;
}

// ---------------------------------------------------------------------------
// RoPE tables (fp64 phase for accuracy)
// ---------------------------------------------------------------------------
__global__ void gen_tables_kernel() {
    int i = blockIdx.x * blockDim.x + threadIdx.x;
    if (i >= T_SEQ * 32) return;
    int t = i >> 5, m = i & 31;
    double invf = exp(-(double)(2 * m) * (log(10000.0) / 64.0));
    double ph = (double)t * invf;
    g_cos[i] = (float)cos(ph);
    g_sin[i] = (float)sin(ph);
}

// ---------------------------------------------------------------------------
// Split fp32 -> (hi, lo) bf16 (x only)
// ---------------------------------------------------------------------------
__global__ void split_kernel(const float* __restrict__ in,
                             __nv_bfloat16* __restrict__ hi,
                             __nv_bfloat16* __restrict__ lo, int n4) {
    int i = blockIdx.x * blockDim.x + threadIdx.x;
    if (i >= n4) return;
    float4 v = ((const float4*)in)[i];
    uint32_t h0, l0, h1, l1;
    split2(v.x, v.y, h0, l0);
    split2(v.z, v.w, h1, l1);
    ((uint32_t*)hi)[i * 2 + 0] = h0;
    ((uint32_t*)hi)[i * 2 + 1] = h1;
    ((uint32_t*)lo)[i * 2 + 0] = l0;
    ((uint32_t*)lo)[i * 2 + 1] = l1;
}

// ---------------------------------------------------------------------------
// Transpose + split: W[K][N] fp32 -> T_hi/T_lo[N][K] bf16
// ---------------------------------------------------------------------------
__global__ void transpose_split_kernel(const float* __restrict__ W,
                                       __nv_bfloat16* __restrict__ th,
                                       __nv_bfloat16* __restrict__ tl,
                                       int K, int N) {
    __shared__ float t[32][33];
    int k0 = blockIdx.y * 32, n0 = blockIdx.x * 32;
    for (int r = threadIdx.y; r < 32; r += 8)
        t[r][threadIdx.x] = W[(size_t)(k0 + r) * N + n0 + threadIdx.x];
    __syncthreads();
    for (int r = threadIdx.y; r < 32; r += 8) {
        float v = t[threadIdx.x][r];
        __nv_bfloat16 h = __float2bfloat16(v);
        __nv_bfloat16 l = __float2bfloat16(v - __bfloat162float(h));
        size_t o = (size_t)(n0 + r) * K + k0 + threadIdx.x;
        th[o] = h;
        tl[o] = l;
    }
}

// ---------------------------------------------------------------------------
// mma.sync split-bf16 GEMM with cp.async double-buffered pipeline.
// C = A[M,K] @ Bt[N,K]^T.  EPI=1 adds RoPE+scale+split epilogue (QKV path).
// ---------------------------------------------------------------------------
#define ASTR 40
#define TILE_BF16 (128 * ASTR)                 /* one 128x32 tile */
#define G_STAGE_B (4 * TILE_BF16 * 2)          /* 40960 B per stage */
#define G_SMEM2 (2 * G_STAGE_B)                /* 81920 B */

template <int EPI>
__global__ __launch_bounds__(256, 2) void gemm_mma_kernel(
    const __nv_bfloat16* __restrict__ Ah, const __nv_bfloat16* __restrict__ Al,
    const __nv_bfloat16* __restrict__ Bh, const __nv_bfloat16* __restrict__ Bl,
    float* __restrict__ C, __nv_bfloat16* __restrict__ Ch,
    __nv_bfloat16* __restrict__ Cl, int N, int K)
{
    extern __shared__ __nv_bfloat16 smg[];
    const uint32_t sbase = smem_u32(smg);

    const int tid = threadIdx.x;
    const int wid = tid >> 5, lid = tid & 31;
    const int wm = (wid & 3) * 32;
    const int wn = (wid >> 2) * 64;

    const size_t aoff0 = (size_t)blockIdx.y * 128 * K;
    const size_t boff0 = (size_t)blockIdx.x * 128 * K;

    // relative ldmatrix addresses (bytes within a stage)
    uint32_t aAddr[2];
#pragma unroll
    for (int mt = 0; mt < 2; mt++)
        aAddr[mt] = ((wm + mt * 16 + (lid & 15)) * ASTR + (lid >> 4) * 8) * 2;
    uint32_t bAddr[4];
#pragma unroll
    for (int p = 0; p < 4; p++)
        bAddr[p] = ((wn + p * 16 + (lid & 7) + (lid >> 4) * 8) * ASTR
                    + ((lid >> 3) & 1) * 8) * 2;

    const int nchunks = K >> 5;

    auto issue = [&](int c, int st) {
        const __nv_bfloat16* srcs[4] = {
            Ah + aoff0 + c * 32, Al + aoff0 + c * 32,
            Bh + boff0 + c * 32, Bl + boff0 + c * 32 };
        const uint32_t d0 = sbase + st * G_STAGE_B;
#pragma unroll
        for (int tI = 0; tI < 4; tI++) {
#pragma unroll
            for (int it = 0; it < 2; it++) {
                int idx = tid + it * 256;
                int row = idx >> 2, kc = (idx & 3) * 8;
                CP16(d0 + (uint32_t)(tI * TILE_BF16 + row * ASTR + kc) * 2,
                     srcs[tI] + (size_t)row * K + kc);
            }
        }
        CP_COMMIT();
    };

    float acc[2][8][4] = {};

    issue(0, 0);
    for (int c = 0; c < nchunks; c++) {
        const int st = c & 1;
        __syncthreads();                       // compute(c-1) done: safe to fill buf st^1
        if (c + 1 < nchunks) { issue(c + 1, st ^ 1); CP_WAIT1(); }
        else                 { CP_WAIT0(); }
        __syncthreads();                       // stage c data visible

        const uint32_t sAh = sbase + st * G_STAGE_B;
        const uint32_t sAl = sAh + TILE_BF16 * 2;
        const uint32_t sBh = sAh + 2 * TILE_BF16 * 2;
        const uint32_t sBl = sAh + 3 * TILE_BF16 * 2;

#pragma unroll
        for (int ks = 0; ks < 2; ks++) {
            const uint32_t kb = ks * 32;
            uint32_t ah[2][4], al[2][4];
#pragma unroll
            for (int mt = 0; mt < 2; mt++) {
                LDSM_X4(ah[mt], sAh + aAddr[mt] + kb);
                LDSM_X4(al[mt], sAl + aAddr[mt] + kb);
            }
#pragma unroll
            for (int p = 0; p < 4; p++) {
                uint32_t bh[4], bl[4];
                LDSM_X4(bh, sBh + bAddr[p] + kb);
                LDSM_X4(bl, sBl + bAddr[p] + kb);
#pragma unroll
                for (int mt = 0; mt < 2; mt++) {
                    MMA16816(acc[mt][2 * p],     ah[mt], bh);
                    MMA16816(acc[mt][2 * p],     ah[mt], bl);
                    MMA16816(acc[mt][2 * p],     al[mt], bh);
                    MMA16816(acc[mt][2 * p + 1], ah[mt], bh + 2);
                    MMA16816(acc[mt][2 * p + 1], ah[mt], bl + 2);
                    MMA16816(acc[mt][2 * p + 1], al[mt], bh + 2);
                }
            }
        }
    }

    const int mbase = blockIdx.y * 128 + wm + (lid >> 2);
    const int nbase = blockIdx.x * 128 + wn + (lid & 3) * 2;
#pragma unroll
    for (int mt = 0; mt < 2; mt++) {
#pragma unroll
        for (int half = 0; half < 2; half++) {
            const int row = mbase + mt * 16 + half * 8;
#pragma unroll
            for (int nt = 0; nt < 8; nt++) {
                const int col = nbase + nt * 8;
                float v0 = acc[mt][nt][2 * half + 0];
                float v1 = acc[mt][nt][2 * half + 1];
                if (EPI == 0) {
                    *(float2*)(C + (size_t)row * N + col) = make_float2(v0, v1);
                } else {
                    if (col < 2048) {                  // rope on q,k
                        int t = row & (T_SEQ - 1);
                        int m0 = col & 31;
                        float c0 = g_cos[t * 32 + m0], s0 = g_sin[t * 32 + m0];
                        float c1 = g_cos[t * 32 + m0 + 1], s1 = g_sin[t * 32 + m0 + 1];
                        float o0 = v0 * c0 - v1 * s0;
                        float o1 = v1 * c1 + v0 * s1;
                        if (col < 1024) { o0 *= 0.125f; o1 *= 0.125f; }
                        v0 = o0; v1 = o1;
                    }
                    uint32_t hi, lo;
                    split2(v0, v1, hi, lo);
                    *(uint32_t*)(Ch + (size_t)row * N + col) = hi;
                    *(uint32_t*)(Cl + (size_t)row * N + col) = lo;
                }
            }
        }
    }
}

// ---------------------------------------------------------------------------
// mma.sync flash attention, split-bf16, cp.async double-buffered K/V.
// CTA: 128 q-rows x one (b,h). 8 warps x m16. K/V chunks of 64.
// ---------------------------------------------------------------------------
#define QSTR 72
#define Q_BF16 (128 * QSTR)
#define KVT (64 * QSTR)
#define KV_STAGE_BF16 (4 * KVT)
#define KV0 (2 * Q_BF16)
#define ATT_SMEM ((2 * Q_BF16 + 2 * KV_STAGE_BF16) * 2)   /* 110592 B */

__global__ __launch_bounds__(256, 2) void attn_mma_kernel(
    const __nv_bfloat16* __restrict__ qh, const __nv_bfloat16* __restrict__ ql,
    __nv_bfloat16* __restrict__ aoh, __nv_bfloat16* __restrict__ aol)
{
    extern __shared__ __nv_bfloat16 sma[];
    const uint32_t sb = smem_u32(sma);
    const int tid = threadIdx.x, wid = tid >> 5, lid = tid & 31;
    const int b = blockIdx.y >> 4, h = blockIdx.y & 15;
    const int q0 = blockIdx.x * 128;
    const size_t rowbase = (size_t)(b * T_SEQ) * QKV_LD;
    const int hc = h * 64;

    auto issue_kv = [&](int s0, int st) {
        const uint32_t d0 = sb + (KV0 + st * KV_STAGE_BF16) * 2;
#pragma unroll
        for (int i = 0; i < 2; i++) {
            int idx = tid + i * 256;                 // 0..511
            int r = idx >> 3, c8 = (idx & 7) * 8;
            size_t gk = rowbase + (size_t)(s0 + r) * QKV_LD + 1024 + hc + c8;
            size_t gv = gk + 1024;
            uint32_t so = (uint32_t)(r * QSTR + c8) * 2;
            CP16(d0 + so,               qh + gk);
            CP16(d0 + KVT * 2 + so,     ql + gk);
            CP16(d0 + 2 * KVT * 2 + so, qh + gv);
            CP16(d0 + 3 * KVT * 2 + so, ql + gv);
        }
        CP_COMMIT();
    };

    // Prologue: Q (hi/lo) + first KV chunk in one cp.async group
    {
#pragma unroll
        for (int i = 0; i < 4; i++) {
            int idx = tid + i * 256;                 // 0..1023
            int r = idx >> 3, c8 = (idx & 7) * 8;
            size_t g = rowbase + (size_t)(q0 + r) * QKV_LD + hc + c8;
            uint32_t so = (uint32_t)(r * QSTR + c8) * 2;
            CP16(sb + so,              qh + g);
            CP16(sb + Q_BF16 * 2 + so, ql + g);
        }
        issue_kv(0, 0);
    }

    const int wm = wid * 16;
    const uint32_t qAddr = sb + ((wm + (lid & 15)) * QSTR + (lid >> 4) * 8) * 2;
    const uint32_t kRel = (((lid & 7) + (lid >> 4) * 8) * QSTR + ((lid >> 3) & 1) * 8) * 2;
    const uint32_t vRel = ((lid & 15) * QSTR + (lid >> 4) * 8) * 2;

    float o[8][4] = {};
    float mrow[2] = {-INFINITY, -INFINITY};
    float lrow[2] = {0.f, 0.f};

    const int nchunks = T_SEQ / 64;
    for (int c = 0; c < nchunks; c++) {
        const int st = c & 1;
        __syncthreads();                         // compute(c-1) done everywhere
        if (c + 1 < nchunks) { issue_kv((c + 1) * 64, st ^ 1); CP_WAIT1(); }
        else                 { CP_WAIT0(); }
        __syncthreads();                         // stage c visible

        const uint32_t kBase = sb + (KV0 + st * KV_STAGE_BF16) * 2 + kRel;
        const uint32_t vBase = sb + (KV0 + st * KV_STAGE_BF16 + 2 * KVT) * 2 + vRel;

        // S = Q K^T  (3-term split)
        float sc[8][4] = {};
#pragma unroll
        for (int ks = 0; ks < 4; ks++) {
            uint32_t ah[4], al[4];
            LDSM_X4(ah, qAddr + ks * 32);
            LDSM_X4(al, qAddr + Q_BF16 * 2 + ks * 32);
#pragma unroll
            for (int p = 0; p < 4; p++) {
                uint32_t bh[4], bl[4];
                uint32_t ka = kBase + p * (16 * QSTR * 2) + ks * 32;
                LDSM_X4(bh, ka);
                LDSM_X4(bl, ka + KVT * 2);
                MMA16816(sc[2 * p],     ah, bh);
                MMA16816(sc[2 * p],     ah, bl);
                MMA16816(sc[2 * p],     al, bh);
                MMA16816(sc[2 * p + 1], ah, bh + 2);
                MMA16816(sc[2 * p + 1], ah, bl + 2);
                MMA16816(sc[2 * p + 1], al, bh + 2);
            }
        }

        // Online softmax (two rows per thread)
#pragma unroll
        for (int hr = 0; hr < 2; hr++) {
            float mx = -INFINITY;
#pragma unroll
            for (int t = 0; t < 8; t++)
                mx = fmaxf(mx, fmaxf(sc[t][2 * hr], sc[t][2 * hr + 1]));
            mx = fmaxf(mx, __shfl_xor_sync(0xffffffffu, mx, 1));
            mx = fmaxf(mx, __shfl_xor_sync(0xffffffffu, mx, 2));
            float mnew = fmaxf(mrow[hr], mx);
            float alpha = __expf(mrow[hr] - mnew);
            float rs = 0.f;
#pragma unroll
            for (int t = 0; t < 8; t++) {
                float e0 = __expf(sc[t][2 * hr] - mnew);
                float e1 = __expf(sc[t][2 * hr + 1] - mnew);
                sc[t][2 * hr] = e0;
                sc[t][2 * hr + 1] = e1;
                rs += e0 + e1;
            }
            rs += __shfl_xor_sync(0xffffffffu, rs, 1);
            rs += __shfl_xor_sync(0xffffffffu, rs, 2);
            lrow[hr] = lrow[hr] * alpha + rs;
            mrow[hr] = mnew;
#pragma unroll
            for (int t = 0; t < 8; t++) {
                o[t][2 * hr] *= alpha;
                o[t][2 * hr + 1] *= alpha;
            }
        }

        // P -> split bf16 A-fragments
        uint32_t ph[4][4], pl[4][4];
#pragma unroll
        for (int ks = 0; ks < 4; ks++) {
            split2(sc[2 * ks][0],     sc[2 * ks][1],     ph[ks][0], pl[ks][0]);
            split2(sc[2 * ks][2],     sc[2 * ks][3],     ph[ks][1], pl[ks][1]);
            split2(sc[2 * ks + 1][0], sc[2 * ks + 1][1], ph[ks][2], pl[ks][2]);
            split2(sc[2 * ks + 1][2], sc[2 * ks + 1][3], ph[ks][3], pl[ks][3]);
        }

        // O += P V  (V via ldmatrix.trans; 3-term split)
#pragma unroll
        for (int ks = 0; ks < 4; ks++) {
#pragma unroll
            for (int p = 0; p < 4; p++) {
                uint32_t vh[4], vl[4];
                uint32_t va = vBase + ks * (16 * QSTR * 2) + p * 32;
                LDSM_X4_T(vh, va);
                LDSM_X4_T(vl, va + KVT * 2);
                MMA16816(o[2 * p],     ph[ks], vh);
                MMA16816(o[2 * p],     ph[ks], vl);
                MMA16816(o[2 * p],     pl[ks], vh);
                MMA16816(o[2 * p + 1], ph[ks], vh + 2);
                MMA16816(o[2 * p + 1], ph[ks], vl + 2);
                MMA16816(o[2 * p + 1], pl[ks], vh + 2);
            }
        }
    }

    // Normalize + split-store to aoh/aol
#pragma unroll
    for (int hr = 0; hr < 2; hr++) {
        int r = q0 + wm + (lid >> 2) + hr * 8;
        float inv = 1.0f / lrow[hr];
        size_t rowoff = (size_t)(b * T_SEQ + r) * D_MODEL + hc + (lid & 3) * 2;
#pragma unroll
        for (int t = 0; t < 8; t++) {
            float v0 = o[t][2 * hr] * inv;
            float v1 = o[t][2 * hr + 1] * inv;
            uint32_t hi, lo;
            split2(v0, v1, hi, lo);
            *(uint32_t*)(aoh + rowoff + t * 8) = hi;
            *(uint32_t*)(aol + rowoff + t * 8) = lo;
        }
    }
}

// ---------------------------------------------------------------------------
// Launch
// ---------------------------------------------------------------------------
extern "C" void kernel_launch(void* const* d_in, const int* in_sizes, int n_in,
                              void* d_out, int out_size) {
    const float* x    = (const float*)d_in[0];
    const float* Wqkv = (const float*)d_in[1];
    const float* Wout = (const float*)d_in[2];
    float* out = (float*)d_out;

    __nv_bfloat16 *qkvh, *qkvl, *xhi, *xlo, *aohi, *aolo, *wqh, *wql, *woh, *wol;
    cudaGetSymbolAddress((void**)&qkvh, g_qkvh);
    cudaGetSymbolAddress((void**)&qkvl, g_qkvl);
    cudaGetSymbolAddress((void**)&xhi, g_xhi);
    cudaGetSymbolAddress((void**)&xlo, g_xlo);
    cudaGetSymbolAddress((void**)&aohi, g_aohi);
    cudaGetSymbolAddress((void**)&aolo, g_aolo);
    cudaGetSymbolAddress((void**)&wqh, g_wqt_hi);
    cudaGetSymbolAddress((void**)&wql, g_wqt_lo);
    cudaGetSymbolAddress((void**)&woh, g_wot_hi);
    cudaGetSymbolAddress((void**)&wol, g_wot_lo);

    cudaFuncSetAttribute(gemm_mma_kernel<0>,
                         cudaFuncAttributeMaxDynamicSharedMemorySize, G_SMEM2);
    cudaFuncSetAttribute(gemm_mma_kernel<1>,
                         cudaFuncAttributeMaxDynamicSharedMemorySize, G_SMEM2);
    cudaFuncSetAttribute(attn_mma_kernel,
                         cudaFuncAttributeMaxDynamicSharedMemorySize, ATT_SMEM);

    // 1. RoPE tables
    gen_tables_kernel<<<(T_SEQ * 32 + 255) / 256, 256>>>();

    // 2. Prepare operands
    split_kernel<<<(M_ROWS * D_MODEL / 4 + 255) / 256, 256>>>(x, xhi, xlo, M_ROWS * D_MODEL / 4);
    transpose_split_kernel<<<dim3(QKV_LD / 32, D_MODEL / 32), dim3(32, 8)>>>(Wqkv, wqh, wql, D_MODEL, QKV_LD);
    transpose_split_kernel<<<dim3(D_MODEL / 32, D_MODEL / 32), dim3(32, 8)>>>(Wout, woh, wol, D_MODEL, D_MODEL);

    // 3. QKV projection + fused RoPE/scale/split epilogue
    gemm_mma_kernel<1><<<dim3(QKV_LD / 128, M_ROWS / 128), 256, G_SMEM2>>>(
        xhi, xlo, wqh, wql, nullptr, qkvh, qkvl, QKV_LD, D_MODEL);

    // 4. Attention (pipelined mma.sync flash, split-bf16)
    attn_mma_kernel<<<dim3(T_SEQ / 128, B_BATCH * H_HEADS), 256, ATT_SMEM>>>(
        qkvh, qkvl, aohi, aolo);

    // 5. Output projection
    gemm_mma_kernel<0><<<dim3(D_MODEL / 128, M_ROWS / 128), 256, G_SMEM2>>>(
        aohi, aolo, woh, wol, out, nullptr, nullptr, D_MODEL, D_MODEL);
}

// round 6
// speedup vs baseline: 3.9493x; 1.3321x over previous
#include <cuda_runtime.h>
#include <cuda_bf16.h>
#include <cuda_fp16.h>
#include <math.h>
#include <stdint.h>

#define T_SEQ 2048
#define B_BATCH 2
#define D_MODEL 1024
#define H_HEADS 16
#define M_ROWS 4096          /* B*T */
#define QKV_LD 3072

// ---------------------------------------------------------------------------
// Scratch (static __device__ — no allocations allowed anywhere)
// ---------------------------------------------------------------------------
__device__ __half g_qkvf[(size_t)M_ROWS * QKV_LD];          // fp16 qkv (rope+scale)
__device__ __nv_bfloat16 g_xhi[(size_t)M_ROWS * D_MODEL];
__device__ __nv_bfloat16 g_xlo[(size_t)M_ROWS * D_MODEL];
__device__ __nv_bfloat16 g_aohi[(size_t)M_ROWS * D_MODEL];
__device__ __nv_bfloat16 g_aolo[(size_t)M_ROWS * D_MODEL];
__device__ __nv_bfloat16 g_wqt_hi[(size_t)QKV_LD * D_MODEL];
__device__ __nv_bfloat16 g_wqt_lo[(size_t)QKV_LD * D_MODEL];
__device__ __nv_bfloat16 g_wot_hi[(size_t)D_MODEL * D_MODEL];
__device__ __nv_bfloat16 g_wot_lo[(size_t)D_MODEL * D_MODEL];
__device__ float g_cos[T_SEQ * 32];
__device__ float g_sin[T_SEQ * 32];

// ---------------------------------------------------------------------------
// Helpers
// ---------------------------------------------------------------------------
__device__ __forceinline__ uint32_t smem_u32(const void* p) {
    uint32_t a;
    asm("{ .reg .u64 t; cvta.to.shared.u64 t, %1; cvt.u32.u64 %0, t; }"
        : "=r"(a) : "l"(p));
    return a;
}

#define CP16(dst, src)                                                       \
    asm volatile("cp.async.cg.shared.global [%0], [%1], 16;"                 \
        :: "r"(dst), "l"(src))
#define CP_COMMIT() asm volatile("cp.async.commit_group;" ::: "memory")
#define CP_WAIT0()  asm volatile("cp.async.wait_group 0;" ::: "memory")
#define CP_WAIT1()  asm volatile("cp.async.wait_group 1;" ::: "memory")

#define LDSM_X4(r, addr)                                                     \
    asm volatile("ldmatrix.sync.aligned.m8n8.x4.shared.b16 {%0,%1,%2,%3}, [%4];" \
        : "=r"((r)[0]), "=r"((r)[1]), "=r"((r)[2]), "=r"((r)[3])             \
        : "r"(addr))

#define LDSM_X4_T(r, addr)                                                   \
    asm volatile("ldmatrix.sync.aligned.m8n8.x4.trans.shared.b16 {%0,%1,%2,%3}, [%4];" \
        : "=r"((r)[0]), "=r"((r)[1]), "=r"((r)[2]), "=r"((r)[3])             \
        : "r"(addr))

#define MMA16816(c, a, b)                                                    \
    asm volatile("mma.sync.aligned.m16n8k16.row.col.f32.bf16.bf16.f32 "      \
        "{%0,%1,%2,%3}, {%4,%5,%6,%7}, {%8,%9}, {%0,%1,%2,%3};"              \
        : "+f"((c)[0]), "+f"((c)[1]), "+f"((c)[2]), "+f"((c)[3])             \
        : "r"((a)[0]), "r"((a)[1]), "r"((a)[2]), "r"((a)[3]),                \
          "r"((b)[0]), "r"((b)[1]))

#define MMA16816H(c, a, b)                                                   \
    asm volatile("mma.sync.aligned.m16n8k16.row.col.f32.f16.f16.f32 "        \
        "{%0,%1,%2,%3}, {%4,%5,%6,%7}, {%8,%9}, {%0,%1,%2,%3};"              \
        : "+f"((c)[0]), "+f"((c)[1]), "+f"((c)[2]), "+f"((c)[3])             \
        : "r"((a)[0]), "r"((a)[1]), "r"((a)[2]), "r"((a)[3]),                \
          "r"((b)[0]), "r"((b)[1]))

__device__ __forceinline__ void split2(float a, float b, uint32_t& hi, uint32_t& lo) {
    __nv_bfloat16 ha = __float2bfloat16(a), hb = __float2bfloat16(b);
    __nv_bfloat16 la = __float2bfloat16(a - __bfloat162float(ha));
    __nv_bfloat16 lb = __float2bfloat16(b - __bfloat162float(hb));
    __nv_bfloat162 th(ha, hb), tl(la, lb);
    hi = *(uint32_t*)&th;
    lo = *(uint32_t*)&tl;
}
__device__ __forceinline__ uint32_t packh(float a, float b) {
    __half2 t = __floats2half2_rn(a, b);
    return *(uint32_t*)&t;
}

// ---------------------------------------------------------------------------
// RoPE tables (fp64 phase for accuracy)
// ---------------------------------------------------------------------------
__global__ void gen_tables_kernel() {
    int i = blockIdx.x * blockDim.x + threadIdx.x;
    if (i >= T_SEQ * 32) return;
    int t = i >> 5, m = i & 31;
    double invf = exp(-(double)(2 * m) * (log(10000.0) / 64.0));
    double ph = (double)t * invf;
    g_cos[i] = (float)cos(ph);
    g_sin[i] = (float)sin(ph);
}

// ---------------------------------------------------------------------------
// Split fp32 -> (hi, lo) bf16 (x only)
// ---------------------------------------------------------------------------
__global__ void split_kernel(const float* __restrict__ in,
                             __nv_bfloat16* __restrict__ hi,
                             __nv_bfloat16* __restrict__ lo, int n4) {
    int i = blockIdx.x * blockDim.x + threadIdx.x;
    if (i >= n4) return;
    float4 v = ((const float4*)in)[i];
    uint32_t h0, l0, h1, l1;
    split2(v.x, v.y, h0, l0);
    split2(v.z, v.w, h1, l1);
    ((uint32_t*)hi)[i * 2 + 0] = h0;
    ((uint32_t*)hi)[i * 2 + 1] = h1;
    ((uint32_t*)lo)[i * 2 + 0] = l0;
    ((uint32_t*)lo)[i * 2 + 1] = l1;
}

// ---------------------------------------------------------------------------
// Transpose + split: W[K][N] fp32 -> T_hi/T_lo[N][K] bf16
// ---------------------------------------------------------------------------
__global__ void transpose_split_kernel(const float* __restrict__ W,
                                       __nv_bfloat16* __restrict__ th,
                                       __nv_bfloat16* __restrict__ tl,
                                       int K, int N) {
    __shared__ float t[32][33];
    int k0 = blockIdx.y * 32, n0 = blockIdx.x * 32;
    for (int r = threadIdx.y; r < 32; r += 8)
        t[r][threadIdx.x] = W[(size_t)(k0 + r) * N + n0 + threadIdx.x];
    __syncthreads();
    for (int r = threadIdx.y; r < 32; r += 8) {
        float v = t[threadIdx.x][r];
        __nv_bfloat16 h = __float2bfloat16(v);
        __nv_bfloat16 l = __float2bfloat16(v - __bfloat162float(h));
        size_t o = (size_t)(n0 + r) * K + k0 + threadIdx.x;
        th[o] = h;
        tl[o] = l;
    }
}

// ---------------------------------------------------------------------------
// mma.sync split-bf16 GEMM with cp.async double-buffered pipeline.
// C = A[M,K] @ Bt[N,K]^T.
// EPI=0: fp32 C out.   EPI=1: RoPE+scale, fp16 out (QKV path).
// ---------------------------------------------------------------------------
#define ASTR 40
#define TILE_BF16 (128 * ASTR)
#define G_STAGE_B (4 * TILE_BF16 * 2)
#define G_SMEM2 (2 * G_STAGE_B)

template <int EPI>
__global__ __launch_bounds__(256, 2) void gemm_mma_kernel(
    const __nv_bfloat16* __restrict__ Ah, const __nv_bfloat16* __restrict__ Al,
    const __nv_bfloat16* __restrict__ Bh, const __nv_bfloat16* __restrict__ Bl,
    float* __restrict__ C, __half* __restrict__ Cf, int N, int K)
{
    extern __shared__ __nv_bfloat16 smg[];
    const uint32_t sbase = smem_u32(smg);

    const int tid = threadIdx.x;
    const int wid = tid >> 5, lid = tid & 31;
    const int wm = (wid & 3) * 32;
    const int wn = (wid >> 2) * 64;

    const size_t aoff0 = (size_t)blockIdx.y * 128 * K;
    const size_t boff0 = (size_t)blockIdx.x * 128 * K;

    uint32_t aAddr[2];
#pragma unroll
    for (int mt = 0; mt < 2; mt++)
        aAddr[mt] = ((wm + mt * 16 + (lid & 15)) * ASTR + (lid >> 4) * 8) * 2;
    uint32_t bAddr[4];
#pragma unroll
    for (int p = 0; p < 4; p++)
        bAddr[p] = ((wn + p * 16 + (lid & 7) + (lid >> 4) * 8) * ASTR
                    + ((lid >> 3) & 1) * 8) * 2;

    const int nchunks = K >> 5;

    auto issue = [&](int c, int st) {
        const __nv_bfloat16* srcs[4] = {
            Ah + aoff0 + c * 32, Al + aoff0 + c * 32,
            Bh + boff0 + c * 32, Bl + boff0 + c * 32 };
        const uint32_t d0 = sbase + st * G_STAGE_B;
#pragma unroll
        for (int tI = 0; tI < 4; tI++) {
#pragma unroll
            for (int it = 0; it < 2; it++) {
                int idx = tid + it * 256;
                int row = idx >> 2, kc = (idx & 3) * 8;
                CP16(d0 + (uint32_t)(tI * TILE_BF16 + row * ASTR + kc) * 2,
                     srcs[tI] + (size_t)row * K + kc);
            }
        }
        CP_COMMIT();
    };

    float acc[2][8][4] = {};

    issue(0, 0);
    for (int c = 0; c < nchunks; c++) {
        const int st = c & 1;
        __syncthreads();
        if (c + 1 < nchunks) { issue(c + 1, st ^ 1); CP_WAIT1(); }
        else                 { CP_WAIT0(); }
        __syncthreads();

        const uint32_t sAh = sbase + st * G_STAGE_B;
        const uint32_t sAl = sAh + TILE_BF16 * 2;
        const uint32_t sBh = sAh + 2 * TILE_BF16 * 2;
        const uint32_t sBl = sAh + 3 * TILE_BF16 * 2;

#pragma unroll
        for (int ks = 0; ks < 2; ks++) {
            const uint32_t kb = ks * 32;
            uint32_t ah[2][4], al[2][4];
#pragma unroll
            for (int mt = 0; mt < 2; mt++) {
                LDSM_X4(ah[mt], sAh + aAddr[mt] + kb);
                LDSM_X4(al[mt], sAl + aAddr[mt] + kb);
            }
#pragma unroll
            for (int p = 0; p < 4; p++) {
                uint32_t bh[4], bl[4];
                LDSM_X4(bh, sBh + bAddr[p] + kb);
                LDSM_X4(bl, sBl + bAddr[p] + kb);
#pragma unroll
                for (int mt = 0; mt < 2; mt++) {
                    MMA16816(acc[mt][2 * p],     ah[mt], bh);
                    MMA16816(acc[mt][2 * p],     ah[mt], bl);
                    MMA16816(acc[mt][2 * p],     al[mt], bh);
                    MMA16816(acc[mt][2 * p + 1], ah[mt], bh + 2);
                    MMA16816(acc[mt][2 * p + 1], ah[mt], bl + 2);
                    MMA16816(acc[mt][2 * p + 1], al[mt], bh + 2);
                }
            }
        }
    }

    const int mbase = blockIdx.y * 128 + wm + (lid >> 2);
    const int nbase = blockIdx.x * 128 + wn + (lid & 3) * 2;
#pragma unroll
    for (int mt = 0; mt < 2; mt++) {
#pragma unroll
        for (int half = 0; half < 2; half++) {
            const int row = mbase + mt * 16 + half * 8;
#pragma unroll
            for (int nt = 0; nt < 8; nt++) {
                const int col = nbase + nt * 8;
                float v0 = acc[mt][nt][2 * half + 0];
                float v1 = acc[mt][nt][2 * half + 1];
                if (EPI == 0) {
                    *(float2*)(C + (size_t)row * N + col) = make_float2(v0, v1);
                } else {
                    if (col < 2048) {                  // rope on q,k
                        int t = row & (T_SEQ - 1);
                        int m0 = col & 31;
                        float c0 = g_cos[t * 32 + m0], s0 = g_sin[t * 32 + m0];
                        float c1 = g_cos[t * 32 + m0 + 1], s1 = g_sin[t * 32 + m0 + 1];
                        float o0 = v0 * c0 - v1 * s0;
                        float o1 = v1 * c1 + v0 * s1;
                        if (col < 1024) { o0 *= 0.125f; o1 *= 0.125f; }
                        v0 = o0; v1 = o1;
                    }
                    *(uint32_t*)(Cf + (size_t)row * N + col) = packh(v0, v1);
                }
            }
        }
    }
}

// ---------------------------------------------------------------------------
// fp16 single-term mma.sync flash attention (cp.async double-buffered K/V).
// CTA: 128 q-rows x one (b,h). 8 warps x m16. K/V chunks of 64.
// Output split to bf16 hi/lo for the 3-term out projection.
// ---------------------------------------------------------------------------
#define QSTR 72
#define Q_ELE (128 * QSTR)
#define KVT (64 * QSTR)
#define KV_STAGE (2 * KVT)
#define ATT_SMEM ((Q_ELE + 2 * KV_STAGE) * 2)   /* 55296 B */

__global__ __launch_bounds__(256, 2) void attn_mma_kernel(
    const __half* __restrict__ qkv,
    __nv_bfloat16* __restrict__ aoh, __nv_bfloat16* __restrict__ aol)
{
    extern __shared__ __half smh[];
    const uint32_t sb = smem_u32(smh);
    const int tid = threadIdx.x, wid = tid >> 5, lid = tid & 31;
    const int b = blockIdx.y >> 4, h = blockIdx.y & 15;
    const int q0 = blockIdx.x * 128;
    const size_t rowbase = (size_t)(b * T_SEQ) * QKV_LD;
    const int hc = h * 64;

    auto issue_kv = [&](int s0, int st) {
        const uint32_t d0 = sb + (Q_ELE + st * KV_STAGE) * 2;
#pragma unroll
        for (int i = 0; i < 2; i++) {
            int idx = tid + i * 256;                 // 0..511
            int r = idx >> 3, c8 = (idx & 7) * 8;
            size_t gk = rowbase + (size_t)(s0 + r) * QKV_LD + 1024 + hc + c8;
            uint32_t so = (uint32_t)(r * QSTR + c8) * 2;
            CP16(d0 + so,           qkv + gk);          // K
            CP16(d0 + KVT * 2 + so, qkv + gk + 1024);   // V
        }
        CP_COMMIT();
    };

    // Prologue: Q + first KV chunk
    {
#pragma unroll
        for (int i = 0; i < 4; i++) {
            int idx = tid + i * 256;                 // 0..1023
            int r = idx >> 3, c8 = (idx & 7) * 8;
            size_t g = rowbase + (size_t)(q0 + r) * QKV_LD + hc + c8;
            CP16(sb + (uint32_t)(r * QSTR + c8) * 2, qkv + g);
        }
        issue_kv(0, 0);
    }

    const int wm = wid * 16;
    const uint32_t qAddr = sb + ((wm + (lid & 15)) * QSTR + (lid >> 4) * 8) * 2;
    const uint32_t kRel = (((lid & 7) + (lid >> 4) * 8) * QSTR + ((lid >> 3) & 1) * 8) * 2;
    const uint32_t vRel = ((lid & 15) * QSTR + (lid >> 4) * 8) * 2;

    float o[8][4] = {};
    float mrow[2] = {-INFINITY, -INFINITY};
    float lrow[2] = {0.f, 0.f};

    const int nchunks = T_SEQ / 64;
    for (int c = 0; c < nchunks; c++) {
        const int st = c & 1;
        __syncthreads();
        if (c + 1 < nchunks) { issue_kv((c + 1) * 64, st ^ 1); CP_WAIT1(); }
        else                 { CP_WAIT0(); }
        __syncthreads();

        const uint32_t kBase = sb + (Q_ELE + st * KV_STAGE) * 2 + kRel;
        const uint32_t vBase = sb + (Q_ELE + st * KV_STAGE + KVT) * 2 + vRel;

        // S = Q K^T  (fp16 single-term)
        float sc[8][4] = {};
#pragma unroll
        for (int ks = 0; ks < 4; ks++) {
            uint32_t ah[4];
            LDSM_X4(ah, qAddr + ks * 32);
#pragma unroll
            for (int p = 0; p < 4; p++) {
                uint32_t bh[4];
                LDSM_X4(bh, kBase + p * (16 * QSTR * 2) + ks * 32);
                MMA16816H(sc[2 * p],     ah, bh);
                MMA16816H(sc[2 * p + 1], ah, bh + 2);
            }
        }

        // Online softmax (two rows per thread)
#pragma unroll
        for (int hr = 0; hr < 2; hr++) {
            float mx = -INFINITY;
#pragma unroll
            for (int t = 0; t < 8; t++)
                mx = fmaxf(mx, fmaxf(sc[t][2 * hr], sc[t][2 * hr + 1]));
            mx = fmaxf(mx, __shfl_xor_sync(0xffffffffu, mx, 1));
            mx = fmaxf(mx, __shfl_xor_sync(0xffffffffu, mx, 2));
            float mnew = fmaxf(mrow[hr], mx);
            float alpha = __expf(mrow[hr] - mnew);
            float rs = 0.f;
#pragma unroll
            for (int t = 0; t < 8; t++) {
                float e0 = __expf(sc[t][2 * hr] - mnew);
                float e1 = __expf(sc[t][2 * hr + 1] - mnew);
                sc[t][2 * hr] = e0;
                sc[t][2 * hr + 1] = e1;
                rs += e0 + e1;
            }
            rs += __shfl_xor_sync(0xffffffffu, rs, 1);
            rs += __shfl_xor_sync(0xffffffffu, rs, 2);
            lrow[hr] = lrow[hr] * alpha + rs;
            mrow[hr] = mnew;
#pragma unroll
            for (int t = 0; t < 8; t++) {
                o[t][2 * hr] *= alpha;
                o[t][2 * hr + 1] *= alpha;
            }
        }

        // P -> fp16 A-fragments (registers line up with S tiles)
        uint32_t ph[4][4];
#pragma unroll
        for (int ks = 0; ks < 4; ks++) {
            ph[ks][0] = packh(sc[2 * ks][0],     sc[2 * ks][1]);
            ph[ks][1] = packh(sc[2 * ks][2],     sc[2 * ks][3]);
            ph[ks][2] = packh(sc[2 * ks + 1][0], sc[2 * ks + 1][1]);
            ph[ks][3] = packh(sc[2 * ks + 1][2], sc[2 * ks + 1][3]);
        }

        // O += P V  (V via ldmatrix.trans)
#pragma unroll
        for (int ks = 0; ks < 4; ks++) {
#pragma unroll
            for (int p = 0; p < 4; p++) {
                uint32_t vh[4];
                LDSM_X4_T(vh, vBase + ks * (16 * QSTR * 2) + p * 32);
                MMA16816H(o[2 * p],     ph[ks], vh);
                MMA16816H(o[2 * p + 1], ph[ks], vh + 2);
            }
        }
    }

    // Normalize + split-store to aoh/aol (bf16 hi/lo for out projection)
#pragma unroll
    for (int hr = 0; hr < 2; hr++) {
        int r = q0 + wm + (lid >> 2) + hr * 8;
        float inv = 1.0f / lrow[hr];
        size_t rowoff = (size_t)(b * T_SEQ + r) * D_MODEL + hc + (lid & 3) * 2;
#pragma unroll
        for (int t = 0; t < 8; t++) {
            float v0 = o[t][2 * hr] * inv;
            float v1 = o[t][2 * hr + 1] * inv;
            uint32_t hi, lo;
            split2(v0, v1, hi, lo);
            *(uint32_t*)(aoh + rowoff + t * 8) = hi;
            *(uint32_t*)(aol + rowoff + t * 8) = lo;
        }
    }
}

// ---------------------------------------------------------------------------
// Launch
// ---------------------------------------------------------------------------
extern "C" void kernel_launch(void* const* d_in, const int* in_sizes, int n_in,
                              void* d_out, int out_size) {
    const float* x    = (const float*)d_in[0];
    const float* Wqkv = (const float*)d_in[1];
    const float* Wout = (const float*)d_in[2];
    float* out = (float*)d_out;

    __half* qkvf;
    __nv_bfloat16 *xhi, *xlo, *aohi, *aolo, *wqh, *wql, *woh, *wol;
    cudaGetSymbolAddress((void**)&qkvf, g_qkvf);
    cudaGetSymbolAddress((void**)&xhi, g_xhi);
    cudaGetSymbolAddress((void**)&xlo, g_xlo);
    cudaGetSymbolAddress((void**)&aohi, g_aohi);
    cudaGetSymbolAddress((void**)&aolo, g_aolo);
    cudaGetSymbolAddress((void**)&wqh, g_wqt_hi);
    cudaGetSymbolAddress((void**)&wql, g_wqt_lo);
    cudaGetSymbolAddress((void**)&woh, g_wot_hi);
    cudaGetSymbolAddress((void**)&wol, g_wot_lo);

    cudaFuncSetAttribute(gemm_mma_kernel<0>,
                         cudaFuncAttributeMaxDynamicSharedMemorySize, G_SMEM2);
    cudaFuncSetAttribute(gemm_mma_kernel<1>,
                         cudaFuncAttributeMaxDynamicSharedMemorySize, G_SMEM2);
    cudaFuncSetAttribute(attn_mma_kernel,
                         cudaFuncAttributeMaxDynamicSharedMemorySize, ATT_SMEM);

    // 1. RoPE tables
    gen_tables_kernel<<<(T_SEQ * 32 + 255) / 256, 256>>>();

    // 2. Prepare operands
    split_kernel<<<(M_ROWS * D_MODEL / 4 + 255) / 256, 256>>>(x, xhi, xlo, M_ROWS * D_MODEL / 4);
    transpose_split_kernel<<<dim3(QKV_LD / 32, D_MODEL / 32), dim3(32, 8)>>>(Wqkv, wqh, wql, D_MODEL, QKV_LD);
    transpose_split_kernel<<<dim3(D_MODEL / 32, D_MODEL / 32), dim3(32, 8)>>>(Wout, woh, wol, D_MODEL, D_MODEL);

    // 3. QKV projection + fused RoPE/scale epilogue -> fp16 qkv
    gemm_mma_kernel<1><<<dim3(QKV_LD / 128, M_ROWS / 128), 256, G_SMEM2>>>(
        xhi, xlo, wqh, wql, nullptr, qkvf, QKV_LD, D_MODEL);

    // 4. Attention (fp16 single-term mma.sync flash)
    attn_mma_kernel<<<dim3(T_SEQ / 128, B_BATCH * H_HEADS), 256, ATT_SMEM>>>(
        qkvf, aohi, aolo);

    // 5. Output projection (3-term bf16)
    gemm_mma_kernel<0><<<dim3(D_MODEL / 128, M_ROWS / 128), 256, G_SMEM2>>>(
        aohi, aolo, woh, wol, out, nullptr, D_MODEL, D_MODEL);
}

// round 7
// speedup vs baseline: 4.8045x; 1.2165x over previous
#include <cuda_runtime.h>
#include <cuda_bf16.h>
#include <cuda_fp16.h>
#include <math.h>
#include <stdint.h>

#define T_SEQ 2048
#define B_BATCH 2
#define D_MODEL 1024
#define H_HEADS 16
#define M_ROWS 4096          /* B*T */
#define QKV_LD 3072

// ---------------------------------------------------------------------------
// Scratch (static __device__ — no allocations allowed anywhere)
// ---------------------------------------------------------------------------
__device__ __half g_qkvf[(size_t)M_ROWS * QKV_LD];          // fp16 qkv (rope+scale)
__device__ __half g_xh[(size_t)M_ROWS * D_MODEL];           // x fp16 hi
__device__ __half g_xl[(size_t)M_ROWS * D_MODEL];           // x fp16 lo
__device__ __half g_aoh[(size_t)M_ROWS * D_MODEL];          // attn out fp16 hi
__device__ __half g_aol[(size_t)M_ROWS * D_MODEL];          // attn out fp16 lo
__device__ __half g_wqt[(size_t)QKV_LD * D_MODEL];          // Wqkv^T fp16
__device__ __half g_wot[(size_t)D_MODEL * D_MODEL];         // Wout^T fp16
__device__ float g_cos[T_SEQ * 32];
__device__ float g_sin[T_SEQ * 32];

// ---------------------------------------------------------------------------
// Helpers
// ---------------------------------------------------------------------------
__device__ __forceinline__ uint32_t smem_u32(const void* p) {
    uint32_t a;
    asm("{ .reg .u64 t; cvta.to.shared.u64 t, %1; cvt.u32.u64 %0, t; }"
        : "=r"(a) : "l"(p));
    return a;
}

#define CP16(dst, src)                                                       \
    asm volatile("cp.async.cg.shared.global [%0], [%1], 16;"                 \
        :: "r"(dst), "l"(src))
#define CP_COMMIT() asm volatile("cp.async.commit_group;" ::: "memory")
#define CP_WAIT0()  asm volatile("cp.async.wait_group 0;" ::: "memory")
#define CP_WAIT1()  asm volatile("cp.async.wait_group 1;" ::: "memory")

#define LDSM_X4(r, addr)                                                     \
    asm volatile("ldmatrix.sync.aligned.m8n8.x4.shared.b16 {%0,%1,%2,%3}, [%4];" \
        : "=r"((r)[0]), "=r"((r)[1]), "=r"((r)[2]), "=r"((r)[3])             \
        : "r"(addr))

#define LDSM_X4_T(r, addr)                                                   \
    asm volatile("ldmatrix.sync.aligned.m8n8.x4.trans.shared.b16 {%0,%1,%2,%3}, [%4];" \
        : "=r"((r)[0]), "=r"((r)[1]), "=r"((r)[2]), "=r"((r)[3])             \
        : "r"(addr))

#define MMA16816H(c, a, b)                                                   \
    asm volatile("mma.sync.aligned.m16n8k16.row.col.f32.f16.f16.f32 "        \
        "{%0,%1,%2,%3}, {%4,%5,%6,%7}, {%8,%9}, {%0,%1,%2,%3};"              \
        : "+f"((c)[0]), "+f"((c)[1]), "+f"((c)[2]), "+f"((c)[3])             \
        : "r"((a)[0]), "r"((a)[1]), "r"((a)[2]), "r"((a)[3]),                \
          "r"((b)[0]), "r"((b)[1]))

__device__ __forceinline__ uint32_t packh(float a, float b) {
    __half2 t = __floats2half2_rn(a, b);
    return *(uint32_t*)&t;
}
__device__ __forceinline__ void splith2(float a, float b, uint32_t& hi, uint32_t& lo) {
    __half ha = __float2half_rn(a), hb = __float2half_rn(b);
    __half la = __float2half_rn(a - __half2float(ha));
    __half lb = __float2half_rn(b - __half2float(hb));
    __half2 th(ha, hb), tl(la, lb);
    hi = *(uint32_t*)&th;
    lo = *(uint32_t*)&tl;
}

// ---------------------------------------------------------------------------
// RoPE tables (fp64 phase for accuracy)
// ---------------------------------------------------------------------------
__global__ void gen_tables_kernel() {
    int i = blockIdx.x * blockDim.x + threadIdx.x;
    if (i >= T_SEQ * 32) return;
    int t = i >> 5, m = i & 31;
    double invf = exp(-(double)(2 * m) * (log(10000.0) / 64.0));
    double ph = (double)t * invf;
    g_cos[i] = (float)cos(ph);
    g_sin[i] = (float)sin(ph);
}

// ---------------------------------------------------------------------------
// Split fp32 -> (hi, lo) fp16 (x)
// ---------------------------------------------------------------------------
__global__ void split_kernel(const float* __restrict__ in,
                             __half* __restrict__ hi,
                             __half* __restrict__ lo, int n4) {
    int i = blockIdx.x * blockDim.x + threadIdx.x;
    if (i >= n4) return;
    float4 v = ((const float4*)in)[i];
    uint32_t h0, l0, h1, l1;
    splith2(v.x, v.y, h0, l0);
    splith2(v.z, v.w, h1, l1);
    ((uint32_t*)hi)[i * 2 + 0] = h0;
    ((uint32_t*)hi)[i * 2 + 1] = h1;
    ((uint32_t*)lo)[i * 2 + 0] = l0;
    ((uint32_t*)lo)[i * 2 + 1] = l1;
}

// ---------------------------------------------------------------------------
// Transpose: W[K][N] fp32 -> T[N][K] fp16
// ---------------------------------------------------------------------------
__global__ void transpose_h_kernel(const float* __restrict__ W,
                                   __half* __restrict__ th, int K, int N) {
    __shared__ float t[32][33];
    int k0 = blockIdx.y * 32, n0 = blockIdx.x * 32;
    for (int r = threadIdx.y; r < 32; r += 8)
        t[r][threadIdx.x] = W[(size_t)(k0 + r) * N + n0 + threadIdx.x];
    __syncthreads();
    for (int r = threadIdx.y; r < 32; r += 8)
        th[(size_t)(n0 + r) * K + k0 + threadIdx.x] =
            __float2half_rn(t[threadIdx.x][r]);
}

// ---------------------------------------------------------------------------
// 2-term fp16 GEMM: C = (Ah+Al)[M,K] @ Bt[N,K]^T, cp.async double-buffered.
// EPI=0: fp32 C out.   EPI=1: RoPE+scale, fp16 out (QKV path).
// ---------------------------------------------------------------------------
#define ASTR 40
#define TILE_H (128 * ASTR)                    /* one 128x32 fp16 tile */
#define G_STAGE_B (3 * TILE_H * 2)             /* 30720 B per stage */
#define G_SMEM2 (2 * G_STAGE_B)                /* 61440 B */

template <int EPI>
__global__ __launch_bounds__(256, 2) void gemm_mma_kernel(
    const __half* __restrict__ Ah, const __half* __restrict__ Al,
    const __half* __restrict__ Bh,
    float* __restrict__ C, __half* __restrict__ Cf, int N, int K)
{
    extern __shared__ __half smg[];
    const uint32_t sbase = smem_u32(smg);

    const int tid = threadIdx.x;
    const int wid = tid >> 5, lid = tid & 31;
    const int wm = (wid & 3) * 32;
    const int wn = (wid >> 2) * 64;

    const size_t aoff0 = (size_t)blockIdx.y * 128 * K;
    const size_t boff0 = (size_t)blockIdx.x * 128 * K;

    uint32_t aAddr[2];
#pragma unroll
    for (int mt = 0; mt < 2; mt++)
        aAddr[mt] = ((wm + mt * 16 + (lid & 15)) * ASTR + (lid >> 4) * 8) * 2;
    uint32_t bAddr[4];
#pragma unroll
    for (int p = 0; p < 4; p++)
        bAddr[p] = ((wn + p * 16 + (lid & 7) + (lid >> 4) * 8) * ASTR
                    + ((lid >> 3) & 1) * 8) * 2;

    const int nchunks = K >> 5;

    auto issue = [&](int c, int st) {
        const __half* srcs[3] = {
            Ah + aoff0 + c * 32, Al + aoff0 + c * 32, Bh + boff0 + c * 32 };
        const uint32_t d0 = sbase + st * G_STAGE_B;
#pragma unroll
        for (int tI = 0; tI < 3; tI++) {
#pragma unroll
            for (int it = 0; it < 2; it++) {
                int idx = tid + it * 256;
                int row = idx >> 2, kc = (idx & 3) * 8;
                CP16(d0 + (uint32_t)(tI * TILE_H + row * ASTR + kc) * 2,
                     srcs[tI] + (size_t)row * K + kc);
            }
        }
        CP_COMMIT();
    };

    float acc[2][8][4] = {};

    issue(0, 0);
    for (int c = 0; c < nchunks; c++) {
        const int st = c & 1;
        __syncthreads();
        if (c + 1 < nchunks) { issue(c + 1, st ^ 1); CP_WAIT1(); }
        else                 { CP_WAIT0(); }
        __syncthreads();

        const uint32_t sAh = sbase + st * G_STAGE_B;
        const uint32_t sAl = sAh + TILE_H * 2;
        const uint32_t sBh = sAh + 2 * TILE_H * 2;

#pragma unroll
        for (int ks = 0; ks < 2; ks++) {
            const uint32_t kb = ks * 32;
            uint32_t ah[2][4], al[2][4];
#pragma unroll
            for (int mt = 0; mt < 2; mt++) {
                LDSM_X4(ah[mt], sAh + aAddr[mt] + kb);
                LDSM_X4(al[mt], sAl + aAddr[mt] + kb);
            }
#pragma unroll
            for (int p = 0; p < 4; p++) {
                uint32_t bh[4];
                LDSM_X4(bh, sBh + bAddr[p] + kb);
#pragma unroll
                for (int mt = 0; mt < 2; mt++) {
                    MMA16816H(acc[mt][2 * p],     ah[mt], bh);
                    MMA16816H(acc[mt][2 * p],     al[mt], bh);
                    MMA16816H(acc[mt][2 * p + 1], ah[mt], bh + 2);
                    MMA16816H(acc[mt][2 * p + 1], al[mt], bh + 2);
                }
            }
        }
    }

    const int mbase = blockIdx.y * 128 + wm + (lid >> 2);
    const int nbase = blockIdx.x * 128 + wn + (lid & 3) * 2;
#pragma unroll
    for (int mt = 0; mt < 2; mt++) {
#pragma unroll
        for (int half = 0; half < 2; half++) {
            const int row = mbase + mt * 16 + half * 8;
#pragma unroll
            for (int nt = 0; nt < 8; nt++) {
                const int col = nbase + nt * 8;
                float v0 = acc[mt][nt][2 * half + 0];
                float v1 = acc[mt][nt][2 * half + 1];
                if (EPI == 0) {
                    *(float2*)(C + (size_t)row * N + col) = make_float2(v0, v1);
                } else {
                    if (col < 2048) {                  // rope on q,k
                        int t = row & (T_SEQ - 1);
                        int m0 = col & 31;
                        float c0 = g_cos[t * 32 + m0], s0 = g_sin[t * 32 + m0];
                        float c1 = g_cos[t * 32 + m0 + 1], s1 = g_sin[t * 32 + m0 + 1];
                        float o0 = v0 * c0 - v1 * s0;
                        float o1 = v1 * c1 + v0 * s1;
                        if (col < 1024) { o0 *= 0.125f; o1 *= 0.125f; }
                        v0 = o0; v1 = o1;
                    }
                    *(uint32_t*)(Cf + (size_t)row * N + col) = packh(v0, v1);
                }
            }
        }
    }
}

// ---------------------------------------------------------------------------
// fp16 single-term mma.sync flash attention (cp.async double-buffered K/V).
// CTA: 128 q-rows x one (b,h). 8 warps x m16. K/V chunks of 64.
// Output split to fp16 hi/lo for the 2-term out projection.
// ---------------------------------------------------------------------------
#define QSTR 72
#define Q_ELE (128 * QSTR)
#define KVT (64 * QSTR)
#define KV_STAGE (2 * KVT)
#define ATT_SMEM ((Q_ELE + 2 * KV_STAGE) * 2)   /* 55296 B */

__global__ __launch_bounds__(256, 2) void attn_mma_kernel(
    const __half* __restrict__ qkv,
    __half* __restrict__ aoh, __half* __restrict__ aol)
{
    extern __shared__ __half smh[];
    const uint32_t sb = smem_u32(smh);
    const int tid = threadIdx.x, wid = tid >> 5, lid = tid & 31;
    const int b = blockIdx.y >> 4, h = blockIdx.y & 15;
    const int q0 = blockIdx.x * 128;
    const size_t rowbase = (size_t)(b * T_SEQ) * QKV_LD;
    const int hc = h * 64;

    auto issue_kv = [&](int s0, int st) {
        const uint32_t d0 = sb + (Q_ELE + st * KV_STAGE) * 2;
#pragma unroll
        for (int i = 0; i < 2; i++) {
            int idx = tid + i * 256;
            int r = idx >> 3, c8 = (idx & 7) * 8;
            size_t gk = rowbase + (size_t)(s0 + r) * QKV_LD + 1024 + hc + c8;
            uint32_t so = (uint32_t)(r * QSTR + c8) * 2;
            CP16(d0 + so,           qkv + gk);          // K
            CP16(d0 + KVT * 2 + so, qkv + gk + 1024);   // V
        }
        CP_COMMIT();
    };

    // Prologue: Q + first KV chunk
    {
#pragma unroll
        for (int i = 0; i < 4; i++) {
            int idx = tid + i * 256;
            int r = idx >> 3, c8 = (idx & 7) * 8;
            size_t g = rowbase + (size_t)(q0 + r) * QKV_LD + hc + c8;
            CP16(sb + (uint32_t)(r * QSTR + c8) * 2, qkv + g);
        }
        issue_kv(0, 0);
    }

    const int wm = wid * 16;
    const uint32_t qAddr = sb + ((wm + (lid & 15)) * QSTR + (lid >> 4) * 8) * 2;
    const uint32_t kRel = (((lid & 7) + (lid >> 4) * 8) * QSTR + ((lid >> 3) & 1) * 8) * 2;
    const uint32_t vRel = ((lid & 15) * QSTR + (lid >> 4) * 8) * 2;

    float o[8][4] = {};
    float mrow[2] = {-INFINITY, -INFINITY};
    float lrow[2] = {0.f, 0.f};

    const int nchunks = T_SEQ / 64;
    for (int c = 0; c < nchunks; c++) {
        const int st = c & 1;
        __syncthreads();
        if (c + 1 < nchunks) { issue_kv((c + 1) * 64, st ^ 1); CP_WAIT1(); }
        else                 { CP_WAIT0(); }
        __syncthreads();

        const uint32_t kBase = sb + (Q_ELE + st * KV_STAGE) * 2 + kRel;
        const uint32_t vBase = sb + (Q_ELE + st * KV_STAGE + KVT) * 2 + vRel;

        // S = Q K^T
        float sc[8][4] = {};
#pragma unroll
        for (int ks = 0; ks < 4; ks++) {
            uint32_t ah[4];
            LDSM_X4(ah, qAddr + ks * 32);
#pragma unroll
            for (int p = 0; p < 4; p++) {
                uint32_t bh[4];
                LDSM_X4(bh, kBase + p * (16 * QSTR * 2) + ks * 32);
                MMA16816H(sc[2 * p],     ah, bh);
                MMA16816H(sc[2 * p + 1], ah, bh + 2);
            }
        }

        // Online softmax (two rows per thread)
#pragma unroll
        for (int hr = 0; hr < 2; hr++) {
            float mx = -INFINITY;
#pragma unroll
            for (int t = 0; t < 8; t++)
                mx = fmaxf(mx, fmaxf(sc[t][2 * hr], sc[t][2 * hr + 1]));
            mx = fmaxf(mx, __shfl_xor_sync(0xffffffffu, mx, 1));
            mx = fmaxf(mx, __shfl_xor_sync(0xffffffffu, mx, 2));
            float mnew = fmaxf(mrow[hr], mx);
            float alpha = __expf(mrow[hr] - mnew);
            float rs = 0.f;
#pragma unroll
            for (int t = 0; t < 8; t++) {
                float e0 = __expf(sc[t][2 * hr] - mnew);
                float e1 = __expf(sc[t][2 * hr + 1] - mnew);
                sc[t][2 * hr] = e0;
                sc[t][2 * hr + 1] = e1;
                rs += e0 + e1;
            }
            rs += __shfl_xor_sync(0xffffffffu, rs, 1);
            rs += __shfl_xor_sync(0xffffffffu, rs, 2);
            lrow[hr] = lrow[hr] * alpha + rs;
            mrow[hr] = mnew;
#pragma unroll
            for (int t = 0; t < 8; t++) {
                o[t][2 * hr] *= alpha;
                o[t][2 * hr + 1] *= alpha;
            }
        }

        // P -> fp16 A-fragments
        uint32_t ph[4][4];
#pragma unroll
        for (int ks = 0; ks < 4; ks++) {
            ph[ks][0] = packh(sc[2 * ks][0],     sc[2 * ks][1]);
            ph[ks][1] = packh(sc[2 * ks][2],     sc[2 * ks][3]);
            ph[ks][2] = packh(sc[2 * ks + 1][0], sc[2 * ks + 1][1]);
            ph[ks][3] = packh(sc[2 * ks + 1][2], sc[2 * ks + 1][3]);
        }

        // O += P V
#pragma unroll
        for (int ks = 0; ks < 4; ks++) {
#pragma unroll
            for (int p = 0; p < 4; p++) {
                uint32_t vh[4];
                LDSM_X4_T(vh, vBase + ks * (16 * QSTR * 2) + p * 32);
                MMA16816H(o[2 * p],     ph[ks], vh);
                MMA16816H(o[2 * p + 1], ph[ks], vh + 2);
            }
        }
    }

    // Normalize + fp16 split-store to aoh/aol
#pragma unroll
    for (int hr = 0; hr < 2; hr++) {
        int r = q0 + wm + (lid >> 2) + hr * 8;
        float inv = 1.0f / lrow[hr];
        size_t rowoff = (size_t)(b * T_SEQ + r) * D_MODEL + hc + (lid & 3) * 2;
#pragma unroll
        for (int t = 0; t < 8; t++) {
            float v0 = o[t][2 * hr] * inv;
            float v1 = o[t][2 * hr + 1] * inv;
            uint32_t hi, lo;
            splith2(v0, v1, hi, lo);
            *(uint32_t*)(aoh + rowoff + t * 8) = hi;
            *(uint32_t*)(aol + rowoff + t * 8) = lo;
        }
    }
}

// ---------------------------------------------------------------------------
// Launch
// ---------------------------------------------------------------------------
extern "C" void kernel_launch(void* const* d_in, const int* in_sizes, int n_in,
                              void* d_out, int out_size) {
    const float* x    = (const float*)d_in[0];
    const float* Wqkv = (const float*)d_in[1];
    const float* Wout = (const float*)d_in[2];
    float* out = (float*)d_out;

    __half *qkvf, *xh, *xl, *aoh, *aol, *wq, *wo;
    cudaGetSymbolAddress((void**)&qkvf, g_qkvf);
    cudaGetSymbolAddress((void**)&xh, g_xh);
    cudaGetSymbolAddress((void**)&xl, g_xl);
    cudaGetSymbolAddress((void**)&aoh, g_aoh);
    cudaGetSymbolAddress((void**)&aol, g_aol);
    cudaGetSymbolAddress((void**)&wq, g_wqt);
    cudaGetSymbolAddress((void**)&wo, g_wot);

    cudaFuncSetAttribute(gemm_mma_kernel<0>,
                         cudaFuncAttributeMaxDynamicSharedMemorySize, G_SMEM2);
    cudaFuncSetAttribute(gemm_mma_kernel<1>,
                         cudaFuncAttributeMaxDynamicSharedMemorySize, G_SMEM2);
    cudaFuncSetAttribute(attn_mma_kernel,
                         cudaFuncAttributeMaxDynamicSharedMemorySize, ATT_SMEM);

    // 1. RoPE tables
    gen_tables_kernel<<<(T_SEQ * 32 + 255) / 256, 256>>>();

    // 2. Prepare operands
    split_kernel<<<(M_ROWS * D_MODEL / 4 + 255) / 256, 256>>>(x, xh, xl, M_ROWS * D_MODEL / 4);
    transpose_h_kernel<<<dim3(QKV_LD / 32, D_MODEL / 32), dim3(32, 8)>>>(Wqkv, wq, D_MODEL, QKV_LD);
    transpose_h_kernel<<<dim3(D_MODEL / 32, D_MODEL / 32), dim3(32, 8)>>>(Wout, wo, D_MODEL, D_MODEL);

    // 3. QKV projection (2-term fp16) + fused RoPE/scale epilogue -> fp16 qkv
    gemm_mma_kernel<1><<<dim3(QKV_LD / 128, M_ROWS / 128), 256, G_SMEM2>>>(
        xh, xl, wq, nullptr, qkvf, QKV_LD, D_MODEL);

    // 4. Attention (fp16 single-term mma.sync flash)
    attn_mma_kernel<<<dim3(T_SEQ / 128, B_BATCH * H_HEADS), 256, ATT_SMEM>>>(
        qkvf, aoh, aol);

    // 5. Output projection (2-term fp16)
    gemm_mma_kernel<0><<<dim3(D_MODEL / 128, M_ROWS / 128), 256, G_SMEM2>>>(
        aoh, aol, wo, out, nullptr, D_MODEL, D_MODEL);
}